// round 1
// baseline (speedup 1.0000x reference)
#include <cuda_runtime.h>
#include <math.h>

#define EMBED 1024
#define HEADS 16
#define DK 64
#define SEQ 2048
#define MAXM 4096

// Scratch (allocation-free rule: __device__ globals)
__device__ float g_q[MAXM * EMBED];
__device__ float g_k[MAXM * EMBED];
__device__ float g_v[MAXM * EMBED];
__device__ float g_a[MAXM * EMBED];

// ---------------------------------------------------------------------------
// C[m,n] = sum_k A[m,k] * B[n,k]   (GEMM-NT, all row-major)
// 128x128 tile, BK=8, 256 threads, 8x8 microtile per thread.
// ---------------------------------------------------------------------------
__device__ __forceinline__ void sgemm_nt_body(
    const float* __restrict__ A, const float* __restrict__ B,
    float* __restrict__ C, int M, int N, int K)
{
    __shared__ float As[8][132];
    __shared__ float Bs[8][132];

    const int tid = threadIdx.x;
    const int tx = tid & 15;       // 0..15 -> column groups
    const int ty = tid >> 4;       // 0..15 -> row groups
    const int row0 = blockIdx.y * 128;
    const int col0 = blockIdx.x * 128;

    const int lr = tid >> 1;          // 0..127 tile row
    const int lk = (tid & 1) * 4;     // 0 or 4

    const float* Aptr = A + (size_t)(row0 + lr) * K + lk;
    const float* Bptr = B + (size_t)(col0 + lr) * K + lk;

    float acc[8][8];
#pragma unroll
    for (int i = 0; i < 8; i++)
#pragma unroll
        for (int j = 0; j < 8; j++) acc[i][j] = 0.0f;

    for (int k0 = 0; k0 < K; k0 += 8) {
        float4 av = *(const float4*)(Aptr + k0);
        float4 bv = *(const float4*)(Bptr + k0);
        As[lk + 0][lr] = av.x; As[lk + 1][lr] = av.y;
        As[lk + 2][lr] = av.z; As[lk + 3][lr] = av.w;
        Bs[lk + 0][lr] = bv.x; Bs[lk + 1][lr] = bv.y;
        Bs[lk + 2][lr] = bv.z; Bs[lk + 3][lr] = bv.w;
        __syncthreads();

#pragma unroll
        for (int kk = 0; kk < 8; kk++) {
            float a[8], b[8];
#pragma unroll
            for (int i = 0; i < 4; i++) {
                a[i]     = As[kk][ty * 4 + i];
                a[4 + i] = As[kk][64 + ty * 4 + i];
                b[i]     = Bs[kk][tx * 4 + i];
                b[4 + i] = Bs[kk][64 + tx * 4 + i];
            }
#pragma unroll
            for (int i = 0; i < 8; i++)
#pragma unroll
                for (int j = 0; j < 8; j++)
                    acc[i][j] = fmaf(a[i], b[j], acc[i][j]);
        }
        __syncthreads();
    }

    // Write 8x8 block: rows {row0 + ty*4+i, row0+64+ty*4+i}, cols {col0+tx*4+j, +64}
#pragma unroll
    for (int i = 0; i < 8; i++) {
        int mi = (i < 4) ? (ty * 4 + i) : (64 + ty * 4 + (i - 4));
        float* cp = C + (size_t)(row0 + mi) * N + col0;
        float4 v0 = make_float4(acc[i][0], acc[i][1], acc[i][2], acc[i][3]);
        float4 v1 = make_float4(acc[i][4], acc[i][5], acc[i][6], acc[i][7]);
        *(float4*)(cp + tx * 4)      = v0;
        *(float4*)(cp + 64 + tx * 4) = v1;
    }
}

// Fused Q/K/V projection: blockIdx.z selects the weight & destination.
__global__ __launch_bounds__(256) void qkv_gemm_kernel(
    const float* __restrict__ x,
    const float* __restrict__ Wq, const float* __restrict__ Wk,
    const float* __restrict__ Wv, int M)
{
    const float* B;
    float* C;
    if (blockIdx.z == 0)      { B = Wq; C = g_q; }
    else if (blockIdx.z == 1) { B = Wk; C = g_k; }
    else                      { B = Wv; C = g_v; }
    sgemm_nt_body(x, B, C, M, EMBED, EMBED);
}

// Output projection: d_out = g_a @ Wo^T
__global__ __launch_bounds__(256) void out_gemm_kernel(
    const float* __restrict__ Wo, float* __restrict__ out, int M)
{
    sgemm_nt_body(g_a, Wo, out, M, EMBED, EMBED);
}

// ---------------------------------------------------------------------------
// Flash attention, fp32, 1 thread = 1 query row, K/V tiled 16 keys in SMEM.
// Fused epilogue: out = w*sin(c) + (1-w)*c, w = sigmoid(qw[h]).
// grid = (S/128, HEADS, B), block = 128
// ---------------------------------------------------------------------------
__global__ __launch_bounds__(128, 1) void attn_kernel(
    const float* __restrict__ qw, int S)
{
    const int h = blockIdx.y;
    const int b = blockIdx.z;
    const int tid = threadIdx.x;
    const int srow = blockIdx.x * 128 + tid;

    __shared__ float Ks[16][64];
    __shared__ float Vs[16][64];

    const size_t base = (size_t)b * S * EMBED + (size_t)h * DK;

    // Load this thread's query row (64 floats) into registers.
    float4 qr[16];
    const float4* qp = (const float4*)(g_q + base + (size_t)srow * EMBED);
#pragma unroll
    for (int i = 0; i < 16; i++) qr[i] = qp[i];

    float o[64];
#pragma unroll
    for (int d = 0; d < 64; d++) o[d] = 0.0f;
    float mx = -1e30f, l = 0.0f;

    const int lrow = tid >> 4;       // 0..7
    const int lcol = tid & 15;       // 0..15 (x float4)

    for (int t0 = 0; t0 < S; t0 += 16) {
        // Cooperative K/V tile load: 16 rows x 64 floats, coalesced float4.
#pragma unroll
        for (int p = 0; p < 2; p++) {
            int r = lrow + p * 8;
            const float4* kp = (const float4*)(g_k + base + (size_t)(t0 + r) * EMBED);
            const float4* vp = (const float4*)(g_v + base + (size_t)(t0 + r) * EMBED);
            float4 kv = kp[lcol];
            float4 vv = vp[lcol];
            *(float4*)&Ks[r][lcol * 4] = kv;
            *(float4*)&Vs[r][lcol * 4] = vv;
        }
        __syncthreads();

        // Scores for 16 keys
        float s[16];
#pragma unroll
        for (int j = 0; j < 16; j++) {
            const float4* kr = (const float4*)&Ks[j][0];
            float sum = 0.0f;
#pragma unroll
            for (int i = 0; i < 16; i++) {
                float4 kk = kr[i];
                sum = fmaf(qr[i].x, kk.x, sum);
                sum = fmaf(qr[i].y, kk.y, sum);
                sum = fmaf(qr[i].z, kk.z, sum);
                sum = fmaf(qr[i].w, kk.w, sum);
            }
            s[j] = sum * 0.125f;   // 1/sqrt(64)
        }

        // Online softmax update
        float mt = s[0];
#pragma unroll
        for (int j = 1; j < 16; j++) mt = fmaxf(mt, s[j]);
        float nm = fmaxf(mx, mt);
        float corr = __expf(mx - nm);
        mx = nm;
        l *= corr;
#pragma unroll
        for (int d = 0; d < 64; d++) o[d] *= corr;

#pragma unroll
        for (int j = 0; j < 16; j++) {
            float p = __expf(s[j] - nm);
            l += p;
#pragma unroll
            for (int d = 0; d < 64; d++)
                o[d] = fmaf(p, Vs[j][d], o[d]);
        }
        __syncthreads();
    }

    const float inv = 1.0f / l;
    const float w = 1.0f / (1.0f + __expf(-qw[h]));
    float* op = g_a + base + (size_t)srow * EMBED;
#pragma unroll
    for (int d = 0; d < 64; d++) {
        float c = o[d] * inv;
        op[d] = w * sinf(c) + (1.0f - w) * c;
    }
}

// ---------------------------------------------------------------------------
extern "C" void kernel_launch(void* const* d_in, const int* in_sizes, int n_in,
                              void* d_out, int out_size)
{
    const float* x  = (const float*)d_in[0];
    const float* Wq = (const float*)d_in[1];
    const float* Wk = (const float*)d_in[2];
    const float* Wv = (const float*)d_in[3];
    const float* Wo = (const float*)d_in[4];
    const float* qw = (const float*)d_in[5];
    float* out = (float*)d_out;

    const int M = in_sizes[0] / EMBED;   // B*S = 4096
    const int S = SEQ;
    const int B = M / S;

    // 1) Q,K,V projections (fused launch)
    {
        dim3 grid(EMBED / 128, M / 128, 3);
        qkv_gemm_kernel<<<grid, 256>>>(x, Wq, Wk, Wv, M);
    }
    // 2) Attention + mix epilogue
    {
        dim3 grid(S / 128, HEADS, B);
        attn_kernel<<<grid, 128>>>(qw, S);
    }
    // 3) Output projection
    {
        dim3 grid(EMBED / 128, M / 128, 1);
        out_gemm_kernel<<<grid, 256>>>(Wo, out, M);
    }
}

// round 3
// speedup vs baseline: 1.2641x; 1.2641x over previous
#include <cuda_runtime.h>
#include <cuda_bf16.h>
#include <math.h>
#include <stdint.h>

#define EMBED 1024
#define HEADS 16
#define DK 64
#define SEQ 2048
#define MAXM 4096

// Scratch (allocation-free rule: __device__ globals)
__device__ float g_q[MAXM * EMBED];
__device__ float g_k[MAXM * EMBED];
__device__ float g_v[MAXM * EMBED];
__device__ float g_a[MAXM * EMBED];

// ===========================================================================
// mma.sync (HMMA) split-bf16 GEMM:  C[m,n] = sum_k A[m,k]*B[n,k]  (GEMM-NT)
// CTA tile 128x128, K-chunk 32, 8 warps (2 m x 4 n), warp tile 64x32.
// A = Ahi + Alo (bf16 split); D += Ahi*Bhi + Ahi*Blo + Alo*Bhi (fp32 acc).
// ===========================================================================
#define TM 128
#define TN 128
#define KCH 32
#define LDT 40                      // padded row stride in bf16 (80 bytes)
#define TILE_B (128 * LDT * 2)      // 10240 bytes per 128x32 bf16 tile
#define STAGE_B (4 * TILE_B)        // Ahi, Alo, Bhi, Blo
#define SMEM_GEMM (2 * STAGE_B)     // 81920 bytes

__device__ __forceinline__ uint32_t smem_u32(const void* p) {
    uint32_t a;
    asm("{ .reg .u64 t; cvta.to.shared.u64 t, %1; cvt.u32.u64 %0, t; }"
        : "=r"(a) : "l"(p));
    return a;
}

__device__ __forceinline__ void ldm_x4(uint32_t* r, uint32_t addr) {
    asm volatile("ldmatrix.sync.aligned.m8n8.x4.shared.b16 {%0,%1,%2,%3}, [%4];"
                 : "=r"(r[0]), "=r"(r[1]), "=r"(r[2]), "=r"(r[3]) : "r"(addr));
}

__device__ __forceinline__ void mma16816(float* d, const uint32_t* a, const uint32_t* b) {
    asm volatile(
        "mma.sync.aligned.m16n8k16.row.col.f32.bf16.bf16.f32 "
        "{%0,%1,%2,%3}, {%4,%5,%6,%7}, {%8,%9}, {%0,%1,%2,%3};"
        : "+f"(d[0]), "+f"(d[1]), "+f"(d[2]), "+f"(d[3])
        : "r"(a[0]), "r"(a[1]), "r"(a[2]), "r"(a[3]), "r"(b[0]), "r"(b[1]));
}

__device__ __forceinline__ uint32_t packbf(__nv_bfloat16 a, __nv_bfloat16 b) {
    return (uint32_t)__bfloat16_as_ushort(a) | ((uint32_t)__bfloat16_as_ushort(b) << 16);
}

__device__ __forceinline__ void cvt_split4(float4 v, uint2& h, uint2& l) {
    __nv_bfloat16 h0 = __float2bfloat16(v.x);
    __nv_bfloat16 h1 = __float2bfloat16(v.y);
    __nv_bfloat16 h2 = __float2bfloat16(v.z);
    __nv_bfloat16 h3 = __float2bfloat16(v.w);
    __nv_bfloat16 l0 = __float2bfloat16(v.x - __bfloat162float(h0));
    __nv_bfloat16 l1 = __float2bfloat16(v.y - __bfloat162float(h1));
    __nv_bfloat16 l2 = __float2bfloat16(v.z - __bfloat162float(h2));
    __nv_bfloat16 l3 = __float2bfloat16(v.w - __bfloat162float(h3));
    h.x = packbf(h0, h1); h.y = packbf(h2, h3);
    l.x = packbf(l0, l1); l.y = packbf(l2, l3);
}

__device__ __forceinline__ void gemm_tc_body(
    const float* __restrict__ A, const float* __restrict__ B, float* __restrict__ C)
{
    extern __shared__ char smem[];
    const uint32_t sbase = smem_u32(smem);
    const int tid  = threadIdx.x;
    const int lane = tid & 31;
    const int wid  = tid >> 5;
    const int wm   = wid & 1;        // 0..1 (m)
    const int wn   = wid >> 1;       // 0..3 (n)
    const int m0 = blockIdx.y * TM;
    const int n0 = blockIdx.x * TN;

    const float* Ab = A + (size_t)m0 * EMBED;
    const float* Bb = B + (size_t)n0 * EMBED;

    float acc[4][4][4];
#pragma unroll
    for (int i = 0; i < 4; i++)
#pragma unroll
        for (int j = 0; j < 4; j++)
#pragma unroll
            for (int r = 0; r < 4; r++) acc[i][j][r] = 0.0f;

    // per-thread load slots: idx = tid + i*256; row = idx>>3, f4col = idx&7
    int lrow[4], lf4[4];
#pragma unroll
    for (int i = 0; i < 4; i++) {
        int idx = tid + i * 256;
        lrow[i] = idx >> 3;
        lf4[i]  = idx & 7;
    }

    float4 pa[4], pb[4];
#pragma unroll
    for (int i = 0; i < 4; i++) {
        pa[i] = *(const float4*)(Ab + (size_t)lrow[i] * EMBED + lf4[i] * 4);
        pb[i] = *(const float4*)(Bb + (size_t)lrow[i] * EMBED + lf4[i] * 4);
    }

    // ldmatrix lane-address components (bytes)
    const int a_row = wm * 64 + (lane & 15);
    const int a_kb  = (lane >> 4) * 16;
    const int b_row = wn * 32 + ((lane >> 4) & 1) * 8 + (lane & 7);
    const int b_kb  = ((lane >> 3) & 1) * 16;

    const int NCHUNK = EMBED / KCH;   // 32
    for (int c = 0; c < NCHUNK; ++c) {
        const int p = c & 1;
        char* st = smem + p * STAGE_B;

        // store prefetched chunk (fp32 -> bf16 hi/lo) into stage p
#pragma unroll
        for (int i = 0; i < 4; i++) {
            uint32_t bo = lrow[i] * (LDT * 2) + lf4[i] * 8;
            uint2 h, l;
            cvt_split4(pa[i], h, l);
            *(uint2*)(st + 0 * TILE_B + bo) = h;
            *(uint2*)(st + 1 * TILE_B + bo) = l;
            cvt_split4(pb[i], h, l);
            *(uint2*)(st + 2 * TILE_B + bo) = h;
            *(uint2*)(st + 3 * TILE_B + bo) = l;
        }
        __syncthreads();

        // prefetch next chunk (overlaps with MMA below)
        if (c + 1 < NCHUNK) {
            const float* An = Ab + (c + 1) * KCH;
            const float* Bn = Bb + (c + 1) * KCH;
#pragma unroll
            for (int i = 0; i < 4; i++) {
                pa[i] = *(const float4*)(An + (size_t)lrow[i] * EMBED + lf4[i] * 4);
                pb[i] = *(const float4*)(Bn + (size_t)lrow[i] * EMBED + lf4[i] * 4);
            }
        }

        const uint32_t sAh = sbase + p * STAGE_B;
        const uint32_t sAl = sAh + TILE_B;
        const uint32_t sBh = sAh + 2 * TILE_B;
        const uint32_t sBl = sAh + 3 * TILE_B;

#pragma unroll
        for (int ks = 0; ks < 2; ++ks) {
            uint32_t ah[4][4], al[4][4];
            uint32_t bh[4][2], bl[4][2];

            const uint32_t akoff = ks * 32 + a_kb;
#pragma unroll
            for (int mi = 0; mi < 4; mi++) {
                uint32_t ro = (uint32_t)(a_row + mi * 16) * (LDT * 2) + akoff;
                ldm_x4(ah[mi], sAh + ro);
                ldm_x4(al[mi], sAl + ro);
            }
            const uint32_t bkoff = ks * 32 + b_kb;
#pragma unroll
            for (int np = 0; np < 2; np++) {
                uint32_t ro = (uint32_t)(b_row + np * 16) * (LDT * 2) + bkoff;
                uint32_t r[4];
                ldm_x4(r, sBh + ro);
                bh[np * 2][0] = r[0]; bh[np * 2][1] = r[1];
                bh[np * 2 + 1][0] = r[2]; bh[np * 2 + 1][1] = r[3];
                ldm_x4(r, sBl + ro);
                bl[np * 2][0] = r[0]; bl[np * 2][1] = r[1];
                bl[np * 2 + 1][0] = r[2]; bl[np * 2 + 1][1] = r[3];
            }

#pragma unroll
            for (int mi = 0; mi < 4; mi++)
#pragma unroll
                for (int ni = 0; ni < 4; ni++) {
                    mma16816(acc[mi][ni], ah[mi], bh[ni]);
                    mma16816(acc[mi][ni], ah[mi], bl[ni]);
                    mma16816(acc[mi][ni], al[mi], bh[ni]);
                }
        }
        __syncthreads();
    }

    // Epilogue: write fp32 accumulators
    const int er = lane >> 2;
    const int ec = (lane & 3) * 2;
#pragma unroll
    for (int mi = 0; mi < 4; mi++) {
#pragma unroll
        for (int ni = 0; ni < 4; ni++) {
            int row = m0 + wm * 64 + mi * 16 + er;
            int col = n0 + wn * 32 + ni * 8 + ec;
            float* cp0 = C + (size_t)row * EMBED + col;
            float* cp1 = C + (size_t)(row + 8) * EMBED + col;
            *(float2*)cp0 = make_float2(acc[mi][ni][0], acc[mi][ni][1]);
            *(float2*)cp1 = make_float2(acc[mi][ni][2], acc[mi][ni][3]);
        }
    }
}

__global__ __launch_bounds__(256, 1) void qkv_tc_kernel(
    const float* __restrict__ x,
    const float* __restrict__ Wq, const float* __restrict__ Wk,
    const float* __restrict__ Wv)
{
    const float* B;
    float* C;
    if (blockIdx.z == 0)      { B = Wq; C = g_q; }
    else if (blockIdx.z == 1) { B = Wk; C = g_k; }
    else                      { B = Wv; C = g_v; }
    gemm_tc_body(x, B, C);
}

__global__ __launch_bounds__(256, 1) void out_tc_kernel(
    const float* __restrict__ Wo, float* __restrict__ out)
{
    gemm_tc_body(g_a, Wo, out);
}

// ---------------------------------------------------------------------------
// Flash attention, fp32, 1 thread = 1 query row, K/V tiled 16 keys in SMEM.
// Fused epilogue: out = w*sin(c) + (1-w)*c, w = sigmoid(qw[h]).
// grid = (S/128, HEADS, B), block = 128
// ---------------------------------------------------------------------------
__global__ __launch_bounds__(128, 1) void attn_kernel(
    const float* __restrict__ qw, int S)
{
    const int h = blockIdx.y;
    const int b = blockIdx.z;
    const int tid = threadIdx.x;
    const int srow = blockIdx.x * 128 + tid;

    __shared__ float Ks[16][64];
    __shared__ float Vs[16][64];

    const size_t base = (size_t)b * S * EMBED + (size_t)h * DK;

    float4 qr[16];
    const float4* qp = (const float4*)(g_q + base + (size_t)srow * EMBED);
#pragma unroll
    for (int i = 0; i < 16; i++) qr[i] = qp[i];

    float o[64];
#pragma unroll
    for (int d = 0; d < 64; d++) o[d] = 0.0f;
    float mx = -1e30f, l = 0.0f;

    const int lrow = tid >> 4;
    const int lcol = tid & 15;

    for (int t0 = 0; t0 < S; t0 += 16) {
#pragma unroll
        for (int p = 0; p < 2; p++) {
            int r = lrow + p * 8;
            const float4* kp = (const float4*)(g_k + base + (size_t)(t0 + r) * EMBED);
            const float4* vp = (const float4*)(g_v + base + (size_t)(t0 + r) * EMBED);
            float4 kv = kp[lcol];
            float4 vv = vp[lcol];
            *(float4*)&Ks[r][lcol * 4] = kv;
            *(float4*)&Vs[r][lcol * 4] = vv;
        }
        __syncthreads();

        float s[16];
#pragma unroll
        for (int j = 0; j < 16; j++) {
            const float4* kr = (const float4*)&Ks[j][0];
            float sum = 0.0f;
#pragma unroll
            for (int i = 0; i < 16; i++) {
                float4 kk = kr[i];
                sum = fmaf(qr[i].x, kk.x, sum);
                sum = fmaf(qr[i].y, kk.y, sum);
                sum = fmaf(qr[i].z, kk.z, sum);
                sum = fmaf(qr[i].w, kk.w, sum);
            }
            s[j] = sum * 0.125f;
        }

        float mt = s[0];
#pragma unroll
        for (int j = 1; j < 16; j++) mt = fmaxf(mt, s[j]);
        float nm = fmaxf(mx, mt);
        float corr = __expf(mx - nm);
        mx = nm;
        l *= corr;
#pragma unroll
        for (int d = 0; d < 64; d++) o[d] *= corr;

#pragma unroll
        for (int j = 0; j < 16; j++) {
            float p = __expf(s[j] - nm);
            l += p;
#pragma unroll
            for (int d = 0; d < 64; d++)
                o[d] = fmaf(p, Vs[j][d], o[d]);
        }
        __syncthreads();
    }

    const float inv = 1.0f / l;
    const float w = 1.0f / (1.0f + __expf(-qw[h]));
    float* op = g_a + base + (size_t)srow * EMBED;
#pragma unroll
    for (int d = 0; d < 64; d++) {
        float c = o[d] * inv;
        op[d] = w * sinf(c) + (1.0f - w) * c;
    }
}

// ---------------------------------------------------------------------------
extern "C" void kernel_launch(void* const* d_in, const int* in_sizes, int n_in,
                              void* d_out, int out_size)
{
    const float* x  = (const float*)d_in[0];
    const float* Wq = (const float*)d_in[1];
    const float* Wk = (const float*)d_in[2];
    const float* Wv = (const float*)d_in[3];
    const float* Wo = (const float*)d_in[4];
    const float* qw = (const float*)d_in[5];
    float* out = (float*)d_out;

    const int M = in_sizes[0] / EMBED;   // B*S = 4096
    const int S = SEQ;
    const int B = M / S;

    static bool attr_done = false;
    if (!attr_done) {
        cudaFuncSetAttribute(qkv_tc_kernel, cudaFuncAttributeMaxDynamicSharedMemorySize, SMEM_GEMM);
        cudaFuncSetAttribute(out_tc_kernel, cudaFuncAttributeMaxDynamicSharedMemorySize, SMEM_GEMM);
        attr_done = true;
    }

    // 1) Q,K,V projections (HMMA split-bf16)
    {
        dim3 grid(EMBED / TN, M / TM, 3);
        qkv_tc_kernel<<<grid, 256, SMEM_GEMM>>>(x, Wq, Wk, Wv);
    }
    // 2) Attention + mix epilogue
    {
        dim3 grid(S / 128, HEADS, B);
        attn_kernel<<<grid, 128>>>(qw, S);
    }
    // 3) Output projection
    {
        dim3 grid(EMBED / TN, M / TM, 1);
        out_tc_kernel<<<grid, 256, SMEM_GEMM>>>(Wo, out);
    }
}

// round 5
// speedup vs baseline: 2.5478x; 2.0155x over previous
#include <cuda_runtime.h>
#include <cuda_bf16.h>
#include <math.h>
#include <stdint.h>

#define EMBED 1024
#define HEADS 16
#define DK 64
#define SEQ 2048
#define MAXM 4096

// Scratch (allocation-free rule: __device__ globals)
__device__ float g_q[MAXM * EMBED];
__device__ float g_k[MAXM * EMBED];
__device__ float g_v[MAXM * EMBED];
__device__ float g_a[MAXM * EMBED];

// ===========================================================================
// Common helpers
// ===========================================================================
__device__ __forceinline__ uint32_t smem_u32(const void* p) {
    uint32_t a;
    asm("{ .reg .u64 t; cvta.to.shared.u64 t, %1; cvt.u32.u64 %0, t; }"
        : "=r"(a) : "l"(p));
    return a;
}

__device__ __forceinline__ void ldm_x4(uint32_t* r, uint32_t addr) {
    asm volatile("ldmatrix.sync.aligned.m8n8.x4.shared.b16 {%0,%1,%2,%3}, [%4];"
                 : "=r"(r[0]), "=r"(r[1]), "=r"(r[2]), "=r"(r[3]) : "r"(addr));
}

__device__ __forceinline__ void ldm_x4_t(uint32_t* r, uint32_t addr) {
    asm volatile("ldmatrix.sync.aligned.m8n8.x4.trans.shared.b16 {%0,%1,%2,%3}, [%4];"
                 : "=r"(r[0]), "=r"(r[1]), "=r"(r[2]), "=r"(r[3]) : "r"(addr));
}

__device__ __forceinline__ void mma16816(float* d, const uint32_t* a, const uint32_t* b) {
    asm volatile(
        "mma.sync.aligned.m16n8k16.row.col.f32.bf16.bf16.f32 "
        "{%0,%1,%2,%3}, {%4,%5,%6,%7}, {%8,%9}, {%0,%1,%2,%3};"
        : "+f"(d[0]), "+f"(d[1]), "+f"(d[2]), "+f"(d[3])
        : "r"(a[0]), "r"(a[1]), "r"(a[2]), "r"(a[3]), "r"(b[0]), "r"(b[1]));
}

__device__ __forceinline__ uint32_t packbf(__nv_bfloat16 a, __nv_bfloat16 b) {
    return (uint32_t)__bfloat16_as_ushort(a) | ((uint32_t)__bfloat16_as_ushort(b) << 16);
}

__device__ __forceinline__ void cvt_split4(float4 v, uint2& h, uint2& l) {
    __nv_bfloat16 h0 = __float2bfloat16(v.x);
    __nv_bfloat16 h1 = __float2bfloat16(v.y);
    __nv_bfloat16 h2 = __float2bfloat16(v.z);
    __nv_bfloat16 h3 = __float2bfloat16(v.w);
    __nv_bfloat16 l0 = __float2bfloat16(v.x - __bfloat162float(h0));
    __nv_bfloat16 l1 = __float2bfloat16(v.y - __bfloat162float(h1));
    __nv_bfloat16 l2 = __float2bfloat16(v.z - __bfloat162float(h2));
    __nv_bfloat16 l3 = __float2bfloat16(v.w - __bfloat162float(h3));
    h.x = packbf(h0, h1); h.y = packbf(h2, h3);
    l.x = packbf(l0, l1); l.y = packbf(l2, l3);
}

__device__ __forceinline__ void cvt_split2(float a, float b, uint32_t& h, uint32_t& l) {
    __nv_bfloat16 h0 = __float2bfloat16(a);
    __nv_bfloat16 h1 = __float2bfloat16(b);
    h = packbf(h0, h1);
    l = packbf(__float2bfloat16(a - __bfloat162float(h0)),
               __float2bfloat16(b - __bfloat162float(h1)));
}

// ===========================================================================
// mma.sync (HMMA) split-bf16 GEMM:  C[m,n] = sum_k A[m,k]*B[n,k]  (GEMM-NT)
// ===========================================================================
#define TM 128
#define TN 128
#define KCH 32
#define LDT 40
#define TILE_B (128 * LDT * 2)
#define STAGE_B (4 * TILE_B)
#define SMEM_GEMM (2 * STAGE_B)

__device__ __forceinline__ void gemm_tc_body(
    const float* __restrict__ A, const float* __restrict__ B, float* __restrict__ C)
{
    extern __shared__ char smem[];
    const uint32_t sbase = smem_u32(smem);
    const int tid  = threadIdx.x;
    const int lane = tid & 31;
    const int wid  = tid >> 5;
    const int wm   = wid & 1;
    const int wn   = wid >> 1;
    const int m0 = blockIdx.y * TM;
    const int n0 = blockIdx.x * TN;

    const float* Ab = A + (size_t)m0 * EMBED;
    const float* Bb = B + (size_t)n0 * EMBED;

    float acc[4][4][4];
#pragma unroll
    for (int i = 0; i < 4; i++)
#pragma unroll
        for (int j = 0; j < 4; j++)
#pragma unroll
            for (int r = 0; r < 4; r++) acc[i][j][r] = 0.0f;

    int lrow[4], lf4[4];
#pragma unroll
    for (int i = 0; i < 4; i++) {
        int idx = tid + i * 256;
        lrow[i] = idx >> 3;
        lf4[i]  = idx & 7;
    }

    float4 pa[4], pb[4];
#pragma unroll
    for (int i = 0; i < 4; i++) {
        pa[i] = *(const float4*)(Ab + (size_t)lrow[i] * EMBED + lf4[i] * 4);
        pb[i] = *(const float4*)(Bb + (size_t)lrow[i] * EMBED + lf4[i] * 4);
    }

    const int a_row = wm * 64 + (lane & 15);
    const int a_kb  = (lane >> 4) * 16;
    const int b_row = wn * 32 + ((lane >> 4) & 1) * 8 + (lane & 7);
    const int b_kb  = ((lane >> 3) & 1) * 16;

    const int NCHUNK = EMBED / KCH;
    for (int c = 0; c < NCHUNK; ++c) {
        const int p = c & 1;
        char* st = smem + p * STAGE_B;

#pragma unroll
        for (int i = 0; i < 4; i++) {
            uint32_t bo = lrow[i] * (LDT * 2) + lf4[i] * 8;
            uint2 h, l;
            cvt_split4(pa[i], h, l);
            *(uint2*)(st + 0 * TILE_B + bo) = h;
            *(uint2*)(st + 1 * TILE_B + bo) = l;
            cvt_split4(pb[i], h, l);
            *(uint2*)(st + 2 * TILE_B + bo) = h;
            *(uint2*)(st + 3 * TILE_B + bo) = l;
        }
        __syncthreads();

        if (c + 1 < NCHUNK) {
            const float* An = Ab + (c + 1) * KCH;
            const float* Bn = Bb + (c + 1) * KCH;
#pragma unroll
            for (int i = 0; i < 4; i++) {
                pa[i] = *(const float4*)(An + (size_t)lrow[i] * EMBED + lf4[i] * 4);
                pb[i] = *(const float4*)(Bn + (size_t)lrow[i] * EMBED + lf4[i] * 4);
            }
        }

        const uint32_t sAh = sbase + p * STAGE_B;
        const uint32_t sAl = sAh + TILE_B;
        const uint32_t sBh = sAh + 2 * TILE_B;
        const uint32_t sBl = sAh + 3 * TILE_B;

#pragma unroll
        for (int ks = 0; ks < 2; ++ks) {
            uint32_t ah[4][4], al[4][4];
            uint32_t bh[4][2], bl[4][2];

            const uint32_t akoff = ks * 32 + a_kb;
#pragma unroll
            for (int mi = 0; mi < 4; mi++) {
                uint32_t ro = (uint32_t)(a_row + mi * 16) * (LDT * 2) + akoff;
                ldm_x4(ah[mi], sAh + ro);
                ldm_x4(al[mi], sAl + ro);
            }
            const uint32_t bkoff = ks * 32 + b_kb;
#pragma unroll
            for (int np = 0; np < 2; np++) {
                uint32_t ro = (uint32_t)(b_row + np * 16) * (LDT * 2) + bkoff;
                uint32_t r[4];
                ldm_x4(r, sBh + ro);
                bh[np * 2][0] = r[0]; bh[np * 2][1] = r[1];
                bh[np * 2 + 1][0] = r[2]; bh[np * 2 + 1][1] = r[3];
                ldm_x4(r, sBl + ro);
                bl[np * 2][0] = r[0]; bl[np * 2][1] = r[1];
                bl[np * 2 + 1][0] = r[2]; bl[np * 2 + 1][1] = r[3];
            }

#pragma unroll
            for (int mi = 0; mi < 4; mi++)
#pragma unroll
                for (int ni = 0; ni < 4; ni++) {
                    mma16816(acc[mi][ni], ah[mi], bh[ni]);
                    mma16816(acc[mi][ni], ah[mi], bl[ni]);
                    mma16816(acc[mi][ni], al[mi], bh[ni]);
                }
        }
        __syncthreads();
    }

    const int er = lane >> 2;
    const int ec = (lane & 3) * 2;
#pragma unroll
    for (int mi = 0; mi < 4; mi++) {
#pragma unroll
        for (int ni = 0; ni < 4; ni++) {
            int row = m0 + wm * 64 + mi * 16 + er;
            int col = n0 + wn * 32 + ni * 8 + ec;
            float* cp0 = C + (size_t)row * EMBED + col;
            float* cp1 = C + (size_t)(row + 8) * EMBED + col;
            *(float2*)cp0 = make_float2(acc[mi][ni][0], acc[mi][ni][1]);
            *(float2*)cp1 = make_float2(acc[mi][ni][2], acc[mi][ni][3]);
        }
    }
}

__global__ __launch_bounds__(256, 1) void qkv_tc_kernel(
    const float* __restrict__ x,
    const float* __restrict__ Wq, const float* __restrict__ Wk,
    const float* __restrict__ Wv)
{
    const float* B;
    float* C;
    if (blockIdx.z == 0)      { B = Wq; C = g_q; }
    else if (blockIdx.z == 1) { B = Wk; C = g_k; }
    else                      { B = Wv; C = g_v; }
    gemm_tc_body(x, B, C);
}

__global__ __launch_bounds__(256, 1) void out_tc_kernel(
    const float* __restrict__ Wo, float* __restrict__ out)
{
    gemm_tc_body(g_a, Wo, out);
}

// ===========================================================================
// Tensor-core flash attention (split-bf16 HMMA), FA2 register softmax.
// CTA: 128 query rows of one (b,h). *** 256 threads = 8 warps x 16 rows ***
// ===========================================================================
#define LQE 72                       // padded row stride (bf16 elems), 144 B
#define ATILE (128 * LQE * 2)        // 18432 B per 128x64 bf16 tile
#define AQH 0
#define AQL (1 * ATILE)
#define AKH (2 * ATILE)
#define AKL (3 * ATILE)
#define AVH (4 * ATILE)
#define AVL (5 * ATILE)
#define SMEM_ATTN (6 * ATILE)        // 110592 B

__global__ __launch_bounds__(256, 1) void attn_tc_kernel(
    const float* __restrict__ qw)
{
    extern __shared__ char smem[];
    const uint32_t sb = smem_u32(smem);
    const int tid  = threadIdx.x;
    const int lane = tid & 31;
    const int w    = tid >> 5;        // warp 0..7 -> query rows w*16..w*16+15
    const int h = blockIdx.y;
    const int b = blockIdx.z;
    const int q0 = blockIdx.x * 128;

    const size_t base = (size_t)b * SEQ * EMBED + (size_t)h * DK;

    // ---- load Q tile (128x64), scale by 1/8, split hi/lo into SMEM ----
    {
        const float* Qg = g_q + base + (size_t)q0 * EMBED;
#pragma unroll
        for (int i = 0; i < 8; i++) {
            int idx = i * 256 + tid;
            int row = idx >> 4, col = idx & 15;
            float4 v = *(const float4*)(Qg + (size_t)row * EMBED + col * 4);
            v.x *= 0.125f; v.y *= 0.125f; v.z *= 0.125f; v.w *= 0.125f;
            uint2 hh, ll;
            cvt_split4(v, hh, ll);
            uint32_t bo = row * (LQE * 2) + col * 8;
            *(uint2*)(smem + AQH + bo) = hh;
            *(uint2*)(smem + AQL + bo) = ll;
        }
    }
    __syncthreads();

    // ---- Q fragments (A operand), resident in registers ----
    uint32_t qh[4][4], ql[4][4];
    {
        const uint32_t aoff = (uint32_t)(w * 16 + (lane & 15)) * (LQE * 2) + (lane >> 4) * 16;
#pragma unroll
        for (int ks = 0; ks < 4; ks++) {
            ldm_x4(qh[ks], sb + AQH + aoff + ks * 32);
            ldm_x4(ql[ks], sb + AQL + aoff + ks * 32);
        }
    }

    float O[8][4];
#pragma unroll
    for (int i = 0; i < 8; i++)
#pragma unroll
        for (int j = 0; j < 4; j++) O[i][j] = 0.0f;
    float M0 = -1e30f, M1 = -1e30f, L0 = 0.0f, L1 = 0.0f;

    // ldmatrix address components
    const uint32_t kb_row = ((lane >> 4) & 1) * 8 + (lane & 7);   // scores B (non-trans)
    const uint32_t kb_kb  = ((lane >> 3) & 1) * 16;
    const uint32_t vb_row = ((lane >> 3) & 1) * 8 + (lane & 7);   // PV B (trans)
    const uint32_t vb_nb  = (lane >> 4) * 16;

    for (int t0 = 0; t0 < SEQ; t0 += 128) {
        __syncthreads();   // previous iteration's reads done before overwrite

        // ---- load K,V chunk (128x64 each), split hi/lo into SMEM ----
        {
            const float* Kg = g_k + base + (size_t)t0 * EMBED;
            const float* Vg = g_v + base + (size_t)t0 * EMBED;
#pragma unroll
            for (int i = 0; i < 8; i++) {
                int idx = i * 256 + tid;
                int row = idx >> 4, col = idx & 15;
                uint32_t bo = row * (LQE * 2) + col * 8;
                uint2 hh, ll;
                float4 kv = *(const float4*)(Kg + (size_t)row * EMBED + col * 4);
                cvt_split4(kv, hh, ll);
                *(uint2*)(smem + AKH + bo) = hh;
                *(uint2*)(smem + AKL + bo) = ll;
                float4 vv = *(const float4*)(Vg + (size_t)row * EMBED + col * 4);
                cvt_split4(vv, hh, ll);
                *(uint2*)(smem + AVH + bo) = hh;
                *(uint2*)(smem + AVL + bo) = ll;
            }
        }
        __syncthreads();

        // ---- scores: s[16][4] = (Q/8) . K^T  (128 keys) ----
        float s[16][4];
#pragma unroll
        for (int i = 0; i < 16; i++)
#pragma unroll
            for (int j = 0; j < 4; j++) s[i][j] = 0.0f;

#pragma unroll
        for (int ks = 0; ks < 4; ks++) {
#pragma unroll
            for (int kp = 0; kp < 8; kp++) {
                uint32_t ro = (uint32_t)(kp * 16 + kb_row) * (LQE * 2) + kb_kb + ks * 32;
                uint32_t rh[4], rl[4];
                ldm_x4(rh, sb + AKH + ro);
                ldm_x4(rl, sb + AKL + ro);
                uint32_t bh0[2] = { rh[0], rh[1] }, bh1[2] = { rh[2], rh[3] };
                uint32_t bl0[2] = { rl[0], rl[1] }, bl1[2] = { rl[2], rl[3] };
                mma16816(s[2 * kp],     qh[ks], bh0);
                mma16816(s[2 * kp],     qh[ks], bl0);
                mma16816(s[2 * kp],     ql[ks], bh0);
                mma16816(s[2 * kp + 1], qh[ks], bh1);
                mma16816(s[2 * kp + 1], qh[ks], bl1);
                mma16816(s[2 * kp + 1], ql[ks], bh1);
            }
        }

        // ---- online softmax ----
        float rm0 = -1e30f, rm1 = -1e30f;
#pragma unroll
        for (int i = 0; i < 16; i++) {
            rm0 = fmaxf(rm0, fmaxf(s[i][0], s[i][1]));
            rm1 = fmaxf(rm1, fmaxf(s[i][2], s[i][3]));
        }
        rm0 = fmaxf(rm0, __shfl_xor_sync(0xFFFFFFFF, rm0, 1));
        rm0 = fmaxf(rm0, __shfl_xor_sync(0xFFFFFFFF, rm0, 2));
        rm1 = fmaxf(rm1, __shfl_xor_sync(0xFFFFFFFF, rm1, 1));
        rm1 = fmaxf(rm1, __shfl_xor_sync(0xFFFFFFFF, rm1, 2));

        float Mn0 = fmaxf(M0, rm0), Mn1 = fmaxf(M1, rm1);
        float sc0 = __expf(M0 - Mn0), sc1 = __expf(M1 - Mn1);
        M0 = Mn0; M1 = Mn1;
        L0 *= sc0; L1 *= sc1;
#pragma unroll
        for (int i = 0; i < 8; i++) {
            O[i][0] *= sc0; O[i][1] *= sc0;
            O[i][2] *= sc1; O[i][3] *= sc1;
        }
#pragma unroll
        for (int i = 0; i < 16; i++) {
            s[i][0] = __expf(s[i][0] - M0);
            s[i][1] = __expf(s[i][1] - M0);
            s[i][2] = __expf(s[i][2] - M1);
            s[i][3] = __expf(s[i][3] - M1);
            L0 += s[i][0] + s[i][1];
            L1 += s[i][2] + s[i][3];
        }

        // ---- O += P . V  (P split hi/lo from accumulators) ----
#pragma unroll
        for (int ks = 0; ks < 8; ks++) {
            uint32_t ph[4], pl[4];
            cvt_split2(s[2 * ks][0],     s[2 * ks][1],     ph[0], pl[0]);
            cvt_split2(s[2 * ks][2],     s[2 * ks][3],     ph[1], pl[1]);
            cvt_split2(s[2 * ks + 1][0], s[2 * ks + 1][1], ph[2], pl[2]);
            cvt_split2(s[2 * ks + 1][2], s[2 * ks + 1][3], ph[3], pl[3]);

            const uint32_t vro = (uint32_t)(ks * 16 + vb_row) * (LQE * 2) + vb_nb;
#pragma unroll
            for (int ntp = 0; ntp < 4; ntp++) {
                uint32_t rh[4], rl[4];
                ldm_x4_t(rh, sb + AVH + vro + ntp * 32);
                ldm_x4_t(rl, sb + AVL + vro + ntp * 32);
                uint32_t vh0[2] = { rh[0], rh[1] }, vh1[2] = { rh[2], rh[3] };
                uint32_t vl0[2] = { rl[0], rl[1] }, vl1[2] = { rl[2], rl[3] };
                mma16816(O[2 * ntp],     ph, vh0);
                mma16816(O[2 * ntp],     ph, vl0);
                mma16816(O[2 * ntp],     pl, vh0);
                mma16816(O[2 * ntp + 1], ph, vh1);
                mma16816(O[2 * ntp + 1], ph, vl1);
                mma16816(O[2 * ntp + 1], pl, vh1);
            }
        }
    }

    // ---- finalize: reduce L across column-group lanes, normalize, mix ----
    L0 += __shfl_xor_sync(0xFFFFFFFF, L0, 1);
    L0 += __shfl_xor_sync(0xFFFFFFFF, L0, 2);
    L1 += __shfl_xor_sync(0xFFFFFFFF, L1, 1);
    L1 += __shfl_xor_sync(0xFFFFFFFF, L1, 2);
    const float inv0 = 1.0f / L0, inv1 = 1.0f / L1;
    const float wmix = 1.0f / (1.0f + __expf(-qw[h]));

    const int r0 = q0 + w * 16 + (lane >> 2);
    const int c0 = (lane & 3) * 2;
    float* out0 = g_a + base + (size_t)r0 * EMBED + c0;
    float* out1 = g_a + base + (size_t)(r0 + 8) * EMBED + c0;
#pragma unroll
    for (int nt = 0; nt < 8; nt++) {
        float ca = O[nt][0] * inv0, cb = O[nt][1] * inv0;
        float cc = O[nt][2] * inv1, cd = O[nt][3] * inv1;
        *(float2*)(out0 + nt * 8) = make_float2(
            wmix * sinf(ca) + (1.0f - wmix) * ca,
            wmix * sinf(cb) + (1.0f - wmix) * cb);
        *(float2*)(out1 + nt * 8) = make_float2(
            wmix * sinf(cc) + (1.0f - wmix) * cc,
            wmix * sinf(cd) + (1.0f - wmix) * cd);
    }
}

// ---------------------------------------------------------------------------
extern "C" void kernel_launch(void* const* d_in, const int* in_sizes, int n_in,
                              void* d_out, int out_size)
{
    const float* x  = (const float*)d_in[0];
    const float* Wq = (const float*)d_in[1];
    const float* Wk = (const float*)d_in[2];
    const float* Wv = (const float*)d_in[3];
    const float* Wo = (const float*)d_in[4];
    const float* qw = (const float*)d_in[5];
    float* out = (float*)d_out;

    const int M = in_sizes[0] / EMBED;   // B*S = 4096
    const int S = SEQ;
    const int B = M / S;

    static bool attr_done = false;
    if (!attr_done) {
        cudaFuncSetAttribute(qkv_tc_kernel, cudaFuncAttributeMaxDynamicSharedMemorySize, SMEM_GEMM);
        cudaFuncSetAttribute(out_tc_kernel, cudaFuncAttributeMaxDynamicSharedMemorySize, SMEM_GEMM);
        cudaFuncSetAttribute(attn_tc_kernel, cudaFuncAttributeMaxDynamicSharedMemorySize, SMEM_ATTN);
        attr_done = true;
    }

    // 1) Q,K,V projections (HMMA split-bf16)
    {
        dim3 grid(EMBED / TN, M / TM, 3);
        qkv_tc_kernel<<<grid, 256, SMEM_GEMM>>>(x, Wq, Wk, Wv);
    }
    // 2) Tensor-core flash attention + mix epilogue (256 threads = 8 warps!)
    {
        dim3 grid(S / 128, HEADS, B);
        attn_tc_kernel<<<grid, 256, SMEM_ATTN>>>(qw);
    }
    // 3) Output projection
    {
        dim3 grid(EMBED / TN, M / TM, 1);
        out_tc_kernel<<<grid, 256, SMEM_GEMM>>>(Wo, out);
    }
}

// round 6
// speedup vs baseline: 2.7855x; 1.0933x over previous
#include <cuda_runtime.h>
#include <cuda_bf16.h>
#include <math.h>
#include <stdint.h>

#define EMBED 1024
#define HEADS 16
#define DK 64
#define SEQ 2048
#define MAXM 4096

// Scratch (allocation-free rule: __device__ globals)
__device__ float g_q[MAXM * EMBED];
__device__ float g_k[MAXM * EMBED];
__device__ float g_v[MAXM * EMBED];
__device__ float g_a[MAXM * EMBED];

// ===========================================================================
// Common helpers
// ===========================================================================
__device__ __forceinline__ uint32_t smem_u32(const void* p) {
    uint32_t a;
    asm("{ .reg .u64 t; cvta.to.shared.u64 t, %1; cvt.u32.u64 %0, t; }"
        : "=r"(a) : "l"(p));
    return a;
}

__device__ __forceinline__ void ldm_x4(uint32_t* r, uint32_t addr) {
    asm volatile("ldmatrix.sync.aligned.m8n8.x4.shared.b16 {%0,%1,%2,%3}, [%4];"
                 : "=r"(r[0]), "=r"(r[1]), "=r"(r[2]), "=r"(r[3]) : "r"(addr));
}

__device__ __forceinline__ void ldm_x4_t(uint32_t* r, uint32_t addr) {
    asm volatile("ldmatrix.sync.aligned.m8n8.x4.trans.shared.b16 {%0,%1,%2,%3}, [%4];"
                 : "=r"(r[0]), "=r"(r[1]), "=r"(r[2]), "=r"(r[3]) : "r"(addr));
}

__device__ __forceinline__ void mma16816(float* d, const uint32_t* a, const uint32_t* b) {
    asm volatile(
        "mma.sync.aligned.m16n8k16.row.col.f32.bf16.bf16.f32 "
        "{%0,%1,%2,%3}, {%4,%5,%6,%7}, {%8,%9}, {%0,%1,%2,%3};"
        : "+f"(d[0]), "+f"(d[1]), "+f"(d[2]), "+f"(d[3])
        : "r"(a[0]), "r"(a[1]), "r"(a[2]), "r"(a[3]), "r"(b[0]), "r"(b[1]));
}

__device__ __forceinline__ uint32_t packbf(__nv_bfloat16 a, __nv_bfloat16 b) {
    return (uint32_t)__bfloat16_as_ushort(a) | ((uint32_t)__bfloat16_as_ushort(b) << 16);
}

__device__ __forceinline__ void cvt_split4(float4 v, uint2& h, uint2& l) {
    __nv_bfloat16 h0 = __float2bfloat16(v.x);
    __nv_bfloat16 h1 = __float2bfloat16(v.y);
    __nv_bfloat16 h2 = __float2bfloat16(v.z);
    __nv_bfloat16 h3 = __float2bfloat16(v.w);
    __nv_bfloat16 l0 = __float2bfloat16(v.x - __bfloat162float(h0));
    __nv_bfloat16 l1 = __float2bfloat16(v.y - __bfloat162float(h1));
    __nv_bfloat16 l2 = __float2bfloat16(v.z - __bfloat162float(h2));
    __nv_bfloat16 l3 = __float2bfloat16(v.w - __bfloat162float(h3));
    h.x = packbf(h0, h1); h.y = packbf(h2, h3);
    l.x = packbf(l0, l1); l.y = packbf(l2, l3);
}

__device__ __forceinline__ void cvt_split2(float a, float b, uint32_t& h, uint32_t& l) {
    __nv_bfloat16 h0 = __float2bfloat16(a);
    __nv_bfloat16 h1 = __float2bfloat16(b);
    h = packbf(h0, h1);
    l = packbf(__float2bfloat16(a - __bfloat162float(h0)),
               __float2bfloat16(b - __bfloat162float(h1)));
}

// ===========================================================================
// mma.sync split-bf16 GEMM:  C[m,n] = sum_k A[m,k]*B[n,k]  (GEMM-NT)
// CTA 128x128, 512 threads = 16 warps (4m x 4n), warp tile 32x32, KCH 32.
// ===========================================================================
#define TM 128
#define TN 128
#define KCH 32
#define LDT 40
#define TILE_B (128 * LDT * 2)
#define STAGE_B (4 * TILE_B)
#define SMEM_GEMM (2 * STAGE_B)

__device__ __forceinline__ void gemm_tc_body(
    const float* __restrict__ A, const float* __restrict__ B, float* __restrict__ C)
{
    extern __shared__ char smem[];
    const uint32_t sbase = smem_u32(smem);
    const int tid  = threadIdx.x;
    const int lane = tid & 31;
    const int wid  = tid >> 5;       // 0..15
    const int wm   = wid & 3;        // m group
    const int wn   = wid >> 2;       // n group
    const int m0 = blockIdx.y * TM;
    const int n0 = blockIdx.x * TN;

    const float* Ab = A + (size_t)m0 * EMBED;
    const float* Bb = B + (size_t)n0 * EMBED;

    float acc[2][4][4];
#pragma unroll
    for (int i = 0; i < 2; i++)
#pragma unroll
        for (int j = 0; j < 4; j++)
#pragma unroll
            for (int r = 0; r < 4; r++) acc[i][j][r] = 0.0f;

    // 512 threads stage 128x32 fp32 of A and B: 1024 f4 each -> 2 per thread
    int lrow[2], lf4[2];
#pragma unroll
    for (int i = 0; i < 2; i++) {
        int idx = tid + i * 512;
        lrow[i] = idx >> 3;
        lf4[i]  = idx & 7;
    }

    float4 pa[2], pb[2];
#pragma unroll
    for (int i = 0; i < 2; i++) {
        pa[i] = *(const float4*)(Ab + (size_t)lrow[i] * EMBED + lf4[i] * 4);
        pb[i] = *(const float4*)(Bb + (size_t)lrow[i] * EMBED + lf4[i] * 4);
    }

    const int a_row = wm * 32 + (lane & 15);
    const int a_kb  = (lane >> 4) * 16;
    const int b_row = wn * 32 + ((lane >> 4) & 1) * 8 + (lane & 7);
    const int b_kb  = ((lane >> 3) & 1) * 16;

    const int NCHUNK = EMBED / KCH;
    for (int c = 0; c < NCHUNK; ++c) {
        const int p = c & 1;
        char* st = smem + p * STAGE_B;

#pragma unroll
        for (int i = 0; i < 2; i++) {
            uint32_t bo = lrow[i] * (LDT * 2) + lf4[i] * 8;
            uint2 h, l;
            cvt_split4(pa[i], h, l);
            *(uint2*)(st + 0 * TILE_B + bo) = h;
            *(uint2*)(st + 1 * TILE_B + bo) = l;
            cvt_split4(pb[i], h, l);
            *(uint2*)(st + 2 * TILE_B + bo) = h;
            *(uint2*)(st + 3 * TILE_B + bo) = l;
        }
        __syncthreads();

        if (c + 1 < NCHUNK) {
            const float* An = Ab + (c + 1) * KCH;
            const float* Bn = Bb + (c + 1) * KCH;
#pragma unroll
            for (int i = 0; i < 2; i++) {
                pa[i] = *(const float4*)(An + (size_t)lrow[i] * EMBED + lf4[i] * 4);
                pb[i] = *(const float4*)(Bn + (size_t)lrow[i] * EMBED + lf4[i] * 4);
            }
        }

        const uint32_t sAh = sbase + p * STAGE_B;
        const uint32_t sAl = sAh + TILE_B;
        const uint32_t sBh = sAh + 2 * TILE_B;
        const uint32_t sBl = sAh + 3 * TILE_B;

#pragma unroll
        for (int ks = 0; ks < 2; ++ks) {
            uint32_t ah[2][4], al[2][4];
            uint32_t bh[4][2], bl[4][2];

            const uint32_t akoff = ks * 32 + a_kb;
#pragma unroll
            for (int mi = 0; mi < 2; mi++) {
                uint32_t ro = (uint32_t)(a_row + mi * 16) * (LDT * 2) + akoff;
                ldm_x4(ah[mi], sAh + ro);
                ldm_x4(al[mi], sAl + ro);
            }
            const uint32_t bkoff = ks * 32 + b_kb;
#pragma unroll
            for (int np = 0; np < 2; np++) {
                uint32_t ro = (uint32_t)(b_row + np * 16) * (LDT * 2) + bkoff;
                uint32_t r[4];
                ldm_x4(r, sBh + ro);
                bh[np * 2][0] = r[0]; bh[np * 2][1] = r[1];
                bh[np * 2 + 1][0] = r[2]; bh[np * 2 + 1][1] = r[3];
                ldm_x4(r, sBl + ro);
                bl[np * 2][0] = r[0]; bl[np * 2][1] = r[1];
                bl[np * 2 + 1][0] = r[2]; bl[np * 2 + 1][1] = r[3];
            }

#pragma unroll
            for (int mi = 0; mi < 2; mi++)
#pragma unroll
                for (int ni = 0; ni < 4; ni++) {
                    mma16816(acc[mi][ni], ah[mi], bh[ni]);
                    mma16816(acc[mi][ni], ah[mi], bl[ni]);
                    mma16816(acc[mi][ni], al[mi], bh[ni]);
                }
        }
        __syncthreads();
    }

    const int er = lane >> 2;
    const int ec = (lane & 3) * 2;
#pragma unroll
    for (int mi = 0; mi < 2; mi++) {
#pragma unroll
        for (int ni = 0; ni < 4; ni++) {
            int row = m0 + wm * 32 + mi * 16 + er;
            int col = n0 + wn * 32 + ni * 8 + ec;
            float* cp0 = C + (size_t)row * EMBED + col;
            float* cp1 = C + (size_t)(row + 8) * EMBED + col;
            *(float2*)cp0 = make_float2(acc[mi][ni][0], acc[mi][ni][1]);
            *(float2*)cp1 = make_float2(acc[mi][ni][2], acc[mi][ni][3]);
        }
    }
}

__global__ __launch_bounds__(512, 1) void qkv_tc_kernel(
    const float* __restrict__ x,
    const float* __restrict__ Wq, const float* __restrict__ Wk,
    const float* __restrict__ Wv)
{
    const float* B;
    float* C;
    if (blockIdx.z == 0)      { B = Wq; C = g_q; }
    else if (blockIdx.z == 1) { B = Wk; C = g_k; }
    else                      { B = Wv; C = g_v; }
    gemm_tc_body(x, B, C);
}

__global__ __launch_bounds__(512, 1) void out_tc_kernel(
    const float* __restrict__ Wo, float* __restrict__ out)
{
    gemm_tc_body(g_a, Wo, out);
}

// ===========================================================================
// Tensor-core flash attention (split-bf16), 512 threads = 16 warps.
// CTA: 256 query rows of one (b,h); warp w -> rows w*16..w*16+15.
// K/V chunks of 64 keys (shared across 256 q-rows -> half the traffic).
// ===========================================================================
#define LQE 72                       // padded row stride (bf16 elems), 144 B
#define QTILE (256 * LQE * 2)        // 36864 B (256 rows)
#define KTILE (64 * LQE * 2)         // 9216 B  (64 rows)
#define AQH 0
#define AQL QTILE
#define AKH (2 * QTILE)
#define AKL (2 * QTILE + KTILE)
#define AVH (2 * QTILE + 2 * KTILE)
#define AVL (2 * QTILE + 3 * KTILE)
#define SMEM_ATTN (2 * QTILE + 4 * KTILE)   // 110592 B

__global__ __launch_bounds__(512, 1) void attn_tc_kernel(
    const float* __restrict__ qw)
{
    extern __shared__ char smem[];
    const uint32_t sb = smem_u32(smem);
    const int tid  = threadIdx.x;
    const int lane = tid & 31;
    const int w    = tid >> 5;        // warp 0..15 -> query rows w*16..
    const int h = blockIdx.y;
    const int b = blockIdx.z;
    const int q0 = blockIdx.x * 256;

    const size_t base = (size_t)b * SEQ * EMBED + (size_t)h * DK;

    // ---- load Q tile (256x64), scale by 1/8, split hi/lo into SMEM ----
    {
        const float* Qg = g_q + base + (size_t)q0 * EMBED;
#pragma unroll
        for (int i = 0; i < 8; i++) {
            int idx = i * 512 + tid;
            int row = idx >> 4, col = idx & 15;
            float4 v = *(const float4*)(Qg + (size_t)row * EMBED + col * 4);
            v.x *= 0.125f; v.y *= 0.125f; v.z *= 0.125f; v.w *= 0.125f;
            uint2 hh, ll;
            cvt_split4(v, hh, ll);
            uint32_t bo = row * (LQE * 2) + col * 8;
            *(uint2*)(smem + AQH + bo) = hh;
            *(uint2*)(smem + AQL + bo) = ll;
        }
    }
    __syncthreads();

    // ---- Q fragments (A operand), register resident ----
    uint32_t qh[4][4], ql[4][4];
    {
        const uint32_t aoff = (uint32_t)(w * 16 + (lane & 15)) * (LQE * 2) + (lane >> 4) * 16;
#pragma unroll
        for (int ks = 0; ks < 4; ks++) {
            ldm_x4(qh[ks], sb + AQH + aoff + ks * 32);
            ldm_x4(ql[ks], sb + AQL + aoff + ks * 32);
        }
    }

    float O[8][4];
#pragma unroll
    for (int i = 0; i < 8; i++)
#pragma unroll
        for (int j = 0; j < 4; j++) O[i][j] = 0.0f;
    float M0 = -1e30f, M1 = -1e30f, L0 = 0.0f, L1 = 0.0f;

    const uint32_t kb_row = ((lane >> 4) & 1) * 8 + (lane & 7);   // scores B (non-trans)
    const uint32_t kb_kb  = ((lane >> 3) & 1) * 16;
    const uint32_t vb_row = ((lane >> 3) & 1) * 8 + (lane & 7);   // PV B (trans)
    const uint32_t vb_nb  = (lane >> 4) * 16;

    for (int t0 = 0; t0 < SEQ; t0 += 64) {
        __syncthreads();   // previous iteration's reads done before overwrite

        // ---- load K,V chunk (64x64 each), split hi/lo into SMEM ----
        {
            const float* Kg = g_k + base + (size_t)t0 * EMBED;
            const float* Vg = g_v + base + (size_t)t0 * EMBED;
#pragma unroll
            for (int i = 0; i < 2; i++) {
                int idx = i * 512 + tid;
                int row = idx >> 4, col = idx & 15;
                uint32_t bo = row * (LQE * 2) + col * 8;
                uint2 hh, ll;
                float4 kv = *(const float4*)(Kg + (size_t)row * EMBED + col * 4);
                cvt_split4(kv, hh, ll);
                *(uint2*)(smem + AKH + bo) = hh;
                *(uint2*)(smem + AKL + bo) = ll;
                float4 vv = *(const float4*)(Vg + (size_t)row * EMBED + col * 4);
                cvt_split4(vv, hh, ll);
                *(uint2*)(smem + AVH + bo) = hh;
                *(uint2*)(smem + AVL + bo) = ll;
            }
        }
        __syncthreads();

        // ---- scores: s[8][4] = (Q/8) . K^T  (64 keys) ----
        float s[8][4];
#pragma unroll
        for (int i = 0; i < 8; i++)
#pragma unroll
            for (int j = 0; j < 4; j++) s[i][j] = 0.0f;

#pragma unroll
        for (int ks = 0; ks < 4; ks++) {
#pragma unroll
            for (int kp = 0; kp < 4; kp++) {
                uint32_t ro = (uint32_t)(kp * 16 + kb_row) * (LQE * 2) + kb_kb + ks * 32;
                uint32_t rh[4], rl[4];
                ldm_x4(rh, sb + AKH + ro);
                ldm_x4(rl, sb + AKL + ro);
                uint32_t bh0[2] = { rh[0], rh[1] }, bh1[2] = { rh[2], rh[3] };
                uint32_t bl0[2] = { rl[0], rl[1] }, bl1[2] = { rl[2], rl[3] };
                mma16816(s[2 * kp],     qh[ks], bh0);
                mma16816(s[2 * kp],     qh[ks], bl0);
                mma16816(s[2 * kp],     ql[ks], bh0);
                mma16816(s[2 * kp + 1], qh[ks], bh1);
                mma16816(s[2 * kp + 1], qh[ks], bl1);
                mma16816(s[2 * kp + 1], ql[ks], bh1);
            }
        }

        // ---- online softmax ----
        float rm0 = -1e30f, rm1 = -1e30f;
#pragma unroll
        for (int i = 0; i < 8; i++) {
            rm0 = fmaxf(rm0, fmaxf(s[i][0], s[i][1]));
            rm1 = fmaxf(rm1, fmaxf(s[i][2], s[i][3]));
        }
        rm0 = fmaxf(rm0, __shfl_xor_sync(0xFFFFFFFF, rm0, 1));
        rm0 = fmaxf(rm0, __shfl_xor_sync(0xFFFFFFFF, rm0, 2));
        rm1 = fmaxf(rm1, __shfl_xor_sync(0xFFFFFFFF, rm1, 1));
        rm1 = fmaxf(rm1, __shfl_xor_sync(0xFFFFFFFF, rm1, 2));

        float Mn0 = fmaxf(M0, rm0), Mn1 = fmaxf(M1, rm1);
        float sc0 = __expf(M0 - Mn0), sc1 = __expf(M1 - Mn1);
        M0 = Mn0; M1 = Mn1;
        L0 *= sc0; L1 *= sc1;
#pragma unroll
        for (int i = 0; i < 8; i++) {
            O[i][0] *= sc0; O[i][1] *= sc0;
            O[i][2] *= sc1; O[i][3] *= sc1;
        }
#pragma unroll
        for (int i = 0; i < 8; i++) {
            s[i][0] = __expf(s[i][0] - M0);
            s[i][1] = __expf(s[i][1] - M0);
            s[i][2] = __expf(s[i][2] - M1);
            s[i][3] = __expf(s[i][3] - M1);
            L0 += s[i][0] + s[i][1];
            L1 += s[i][2] + s[i][3];
        }

        // ---- O += P . V  (P split hi/lo from accumulators) ----
#pragma unroll
        for (int ks = 0; ks < 4; ks++) {
            uint32_t ph[4], pl[4];
            cvt_split2(s[2 * ks][0],     s[2 * ks][1],     ph[0], pl[0]);
            cvt_split2(s[2 * ks][2],     s[2 * ks][3],     ph[1], pl[1]);
            cvt_split2(s[2 * ks + 1][0], s[2 * ks + 1][1], ph[2], pl[2]);
            cvt_split2(s[2 * ks + 1][2], s[2 * ks + 1][3], ph[3], pl[3]);

            const uint32_t vro = (uint32_t)(ks * 16 + vb_row) * (LQE * 2) + vb_nb;
#pragma unroll
            for (int ntp = 0; ntp < 4; ntp++) {
                uint32_t rh[4], rl[4];
                ldm_x4_t(rh, sb + AVH + vro + ntp * 32);
                ldm_x4_t(rl, sb + AVL + vro + ntp * 32);
                uint32_t vh0[2] = { rh[0], rh[1] }, vh1[2] = { rh[2], rh[3] };
                uint32_t vl0[2] = { rl[0], rl[1] }, vl1[2] = { rl[2], rl[3] };
                mma16816(O[2 * ntp],     ph, vh0);
                mma16816(O[2 * ntp],     ph, vl0);
                mma16816(O[2 * ntp],     pl, vh0);
                mma16816(O[2 * ntp + 1], ph, vh1);
                mma16816(O[2 * ntp + 1], ph, vl1);
                mma16816(O[2 * ntp + 1], pl, vh1);
            }
        }
    }

    // ---- finalize: reduce L, normalize, sin-mix, write ----
    L0 += __shfl_xor_sync(0xFFFFFFFF, L0, 1);
    L0 += __shfl_xor_sync(0xFFFFFFFF, L0, 2);
    L1 += __shfl_xor_sync(0xFFFFFFFF, L1, 1);
    L1 += __shfl_xor_sync(0xFFFFFFFF, L1, 2);
    const float inv0 = 1.0f / L0, inv1 = 1.0f / L1;
    const float wmix = 1.0f / (1.0f + __expf(-qw[h]));

    const int r0 = q0 + w * 16 + (lane >> 2);
    const int c0 = (lane & 3) * 2;
    float* out0 = g_a + base + (size_t)r0 * EMBED + c0;
    float* out1 = g_a + base + (size_t)(r0 + 8) * EMBED + c0;
#pragma unroll
    for (int nt = 0; nt < 8; nt++) {
        float ca = O[nt][0] * inv0, cb = O[nt][1] * inv0;
        float cc = O[nt][2] * inv1, cd = O[nt][3] * inv1;
        *(float2*)(out0 + nt * 8) = make_float2(
            wmix * sinf(ca) + (1.0f - wmix) * ca,
            wmix * sinf(cb) + (1.0f - wmix) * cb);
        *(float2*)(out1 + nt * 8) = make_float2(
            wmix * sinf(cc) + (1.0f - wmix) * cc,
            wmix * sinf(cd) + (1.0f - wmix) * cd);
    }
}

// ---------------------------------------------------------------------------
extern "C" void kernel_launch(void* const* d_in, const int* in_sizes, int n_in,
                              void* d_out, int out_size)
{
    const float* x  = (const float*)d_in[0];
    const float* Wq = (const float*)d_in[1];
    const float* Wk = (const float*)d_in[2];
    const float* Wv = (const float*)d_in[3];
    const float* Wo = (const float*)d_in[4];
    const float* qw = (const float*)d_in[5];
    float* out = (float*)d_out;

    const int M = in_sizes[0] / EMBED;   // B*S = 4096
    const int S = SEQ;
    const int B = M / S;

    static bool attr_done = false;
    if (!attr_done) {
        cudaFuncSetAttribute(qkv_tc_kernel, cudaFuncAttributeMaxDynamicSharedMemorySize, SMEM_GEMM);
        cudaFuncSetAttribute(out_tc_kernel, cudaFuncAttributeMaxDynamicSharedMemorySize, SMEM_GEMM);
        cudaFuncSetAttribute(attn_tc_kernel, cudaFuncAttributeMaxDynamicSharedMemorySize, SMEM_ATTN);
        attr_done = true;
    }

    // 1) Q,K,V projections
    {
        dim3 grid(EMBED / TN, M / TM, 3);
        qkv_tc_kernel<<<grid, 512, SMEM_GEMM>>>(x, Wq, Wk, Wv);
    }
    // 2) Tensor-core flash attention + mix epilogue
    {
        dim3 grid(S / 256, HEADS, B);
        attn_tc_kernel<<<grid, 512, SMEM_ATTN>>>(qw);
    }
    // 3) Output projection
    {
        dim3 grid(EMBED / TN, M / TM, 1);
        out_tc_kernel<<<grid, 512, SMEM_GEMM>>>(Wo, out);
    }
}

// round 7
// speedup vs baseline: 3.0139x; 1.0820x over previous
#include <cuda_runtime.h>
#include <cuda_bf16.h>
#include <math.h>
#include <stdint.h>

#define EMBED 1024
#define HEADS 16
#define DK 64
#define SEQ 2048
#define MAXM 4096

// Scratch (allocation-free rule: __device__ globals)
__device__ float g_q[MAXM * EMBED];
__device__ float g_k[MAXM * EMBED];
__device__ float g_v[MAXM * EMBED];
__device__ float g_a[MAXM * EMBED];

// ===========================================================================
// Common helpers
// ===========================================================================
__device__ __forceinline__ uint32_t smem_u32(const void* p) {
    uint32_t a;
    asm("{ .reg .u64 t; cvta.to.shared.u64 t, %1; cvt.u32.u64 %0, t; }"
        : "=r"(a) : "l"(p));
    return a;
}

__device__ __forceinline__ void ldm_x4(uint32_t* r, uint32_t addr) {
    asm volatile("ldmatrix.sync.aligned.m8n8.x4.shared.b16 {%0,%1,%2,%3}, [%4];"
                 : "=r"(r[0]), "=r"(r[1]), "=r"(r[2]), "=r"(r[3]) : "r"(addr));
}

__device__ __forceinline__ void ldm_x4_t(uint32_t* r, uint32_t addr) {
    asm volatile("ldmatrix.sync.aligned.m8n8.x4.trans.shared.b16 {%0,%1,%2,%3}, [%4];"
                 : "=r"(r[0]), "=r"(r[1]), "=r"(r[2]), "=r"(r[3]) : "r"(addr));
}

__device__ __forceinline__ void mma16816(float* d, const uint32_t* a, const uint32_t* b) {
    asm volatile(
        "mma.sync.aligned.m16n8k16.row.col.f32.bf16.bf16.f32 "
        "{%0,%1,%2,%3}, {%4,%5,%6,%7}, {%8,%9}, {%0,%1,%2,%3};"
        : "+f"(d[0]), "+f"(d[1]), "+f"(d[2]), "+f"(d[3])
        : "r"(a[0]), "r"(a[1]), "r"(a[2]), "r"(a[3]), "r"(b[0]), "r"(b[1]));
}

__device__ __forceinline__ uint32_t packbf(__nv_bfloat16 a, __nv_bfloat16 b) {
    return (uint32_t)__bfloat16_as_ushort(a) | ((uint32_t)__bfloat16_as_ushort(b) << 16);
}

__device__ __forceinline__ void cvt_split4(float4 v, uint2& h, uint2& l) {
    __nv_bfloat16 h0 = __float2bfloat16(v.x);
    __nv_bfloat16 h1 = __float2bfloat16(v.y);
    __nv_bfloat16 h2 = __float2bfloat16(v.z);
    __nv_bfloat16 h3 = __float2bfloat16(v.w);
    __nv_bfloat16 l0 = __float2bfloat16(v.x - __bfloat162float(h0));
    __nv_bfloat16 l1 = __float2bfloat16(v.y - __bfloat162float(h1));
    __nv_bfloat16 l2 = __float2bfloat16(v.z - __bfloat162float(h2));
    __nv_bfloat16 l3 = __float2bfloat16(v.w - __bfloat162float(h3));
    h.x = packbf(h0, h1); h.y = packbf(h2, h3);
    l.x = packbf(l0, l1); l.y = packbf(l2, l3);
}

__device__ __forceinline__ void cvt_split2(float a, float b, uint32_t& h, uint32_t& l) {
    __nv_bfloat16 h0 = __float2bfloat16(a);
    __nv_bfloat16 h1 = __float2bfloat16(b);
    h = packbf(h0, h1);
    l = packbf(__float2bfloat16(a - __bfloat162float(h0)),
               __float2bfloat16(b - __bfloat162float(h1)));
}

// ===========================================================================
// mma.sync split-bf16 GEMM:  C[m,n] = sum_k A[m,k]*B[n,k]  (GEMM-NT)
// CTA 128x128, 512 threads = 16 warps (4m x 4n), warp tile 32x32, KCH 32.
// Single barrier per K-chunk (2-stage SMEM double buffer).
// ===========================================================================
#define TM 128
#define TN 128
#define KCH 32
#define LDT 40
#define TILE_B (128 * LDT * 2)
#define STAGE_B (4 * TILE_B)
#define SMEM_GEMM (2 * STAGE_B)

__device__ __forceinline__ void gemm_tc_body(
    const float* __restrict__ A, const float* __restrict__ B, float* __restrict__ C)
{
    extern __shared__ char smem[];
    const uint32_t sbase = smem_u32(smem);
    const int tid  = threadIdx.x;
    const int lane = tid & 31;
    const int wid  = tid >> 5;       // 0..15
    const int wm   = wid & 3;        // m group
    const int wn   = wid >> 2;       // n group
    const int m0 = blockIdx.y * TM;
    const int n0 = blockIdx.x * TN;

    const float* Ab = A + (size_t)m0 * EMBED;
    const float* Bb = B + (size_t)n0 * EMBED;

    float acc[2][4][4];
#pragma unroll
    for (int i = 0; i < 2; i++)
#pragma unroll
        for (int j = 0; j < 4; j++)
#pragma unroll
            for (int r = 0; r < 4; r++) acc[i][j][r] = 0.0f;

    int lrow[2], lf4[2];
#pragma unroll
    for (int i = 0; i < 2; i++) {
        int idx = tid + i * 512;
        lrow[i] = idx >> 3;
        lf4[i]  = idx & 7;
    }

    float4 pa[2], pb[2];
#pragma unroll
    for (int i = 0; i < 2; i++) {
        pa[i] = *(const float4*)(Ab + (size_t)lrow[i] * EMBED + lf4[i] * 4);
        pb[i] = *(const float4*)(Bb + (size_t)lrow[i] * EMBED + lf4[i] * 4);
    }

    const int a_row = wm * 32 + (lane & 15);
    const int a_kb  = (lane >> 4) * 16;
    const int b_row = wn * 32 + ((lane >> 4) & 1) * 8 + (lane & 7);
    const int b_kb  = ((lane >> 3) & 1) * 16;

    const int NCHUNK = EMBED / KCH;
    for (int c = 0; c < NCHUNK; ++c) {
        const int p = c & 1;
        char* st = smem + p * STAGE_B;

        // store prefetched chunk into stage p
#pragma unroll
        for (int i = 0; i < 2; i++) {
            uint32_t bo = lrow[i] * (LDT * 2) + lf4[i] * 8;
            uint2 h, l;
            cvt_split4(pa[i], h, l);
            *(uint2*)(st + 0 * TILE_B + bo) = h;
            *(uint2*)(st + 1 * TILE_B + bo) = l;
            cvt_split4(pb[i], h, l);
            *(uint2*)(st + 2 * TILE_B + bo) = h;
            *(uint2*)(st + 3 * TILE_B + bo) = l;
        }
        __syncthreads();   // single barrier per chunk

        if (c + 1 < NCHUNK) {
            const float* An = Ab + (c + 1) * KCH;
            const float* Bn = Bb + (c + 1) * KCH;
#pragma unroll
            for (int i = 0; i < 2; i++) {
                pa[i] = *(const float4*)(An + (size_t)lrow[i] * EMBED + lf4[i] * 4);
                pb[i] = *(const float4*)(Bn + (size_t)lrow[i] * EMBED + lf4[i] * 4);
            }
        }

        const uint32_t sAh = sbase + p * STAGE_B;
        const uint32_t sAl = sAh + TILE_B;
        const uint32_t sBh = sAh + 2 * TILE_B;
        const uint32_t sBl = sAh + 3 * TILE_B;

#pragma unroll
        for (int ks = 0; ks < 2; ++ks) {
            uint32_t ah[2][4], al[2][4];
            uint32_t bh[4][2], bl[4][2];

            const uint32_t akoff = ks * 32 + a_kb;
#pragma unroll
            for (int mi = 0; mi < 2; mi++) {
                uint32_t ro = (uint32_t)(a_row + mi * 16) * (LDT * 2) + akoff;
                ldm_x4(ah[mi], sAh + ro);
                ldm_x4(al[mi], sAl + ro);
            }
            const uint32_t bkoff = ks * 32 + b_kb;
#pragma unroll
            for (int np = 0; np < 2; np++) {
                uint32_t ro = (uint32_t)(b_row + np * 16) * (LDT * 2) + bkoff;
                uint32_t r[4];
                ldm_x4(r, sBh + ro);
                bh[np * 2][0] = r[0]; bh[np * 2][1] = r[1];
                bh[np * 2 + 1][0] = r[2]; bh[np * 2 + 1][1] = r[3];
                ldm_x4(r, sBl + ro);
                bl[np * 2][0] = r[0]; bl[np * 2][1] = r[1];
                bl[np * 2 + 1][0] = r[2]; bl[np * 2 + 1][1] = r[3];
            }

#pragma unroll
            for (int mi = 0; mi < 2; mi++)
#pragma unroll
                for (int ni = 0; ni < 4; ni++) {
                    mma16816(acc[mi][ni], ah[mi], bh[ni]);
                    mma16816(acc[mi][ni], ah[mi], bl[ni]);
                    mma16816(acc[mi][ni], al[mi], bh[ni]);
                }
        }
        // no trailing barrier: next store targets the other stage; the next
        // sync orders all warps' stores before anyone computes on it.
    }

    const int er = lane >> 2;
    const int ec = (lane & 3) * 2;
#pragma unroll
    for (int mi = 0; mi < 2; mi++) {
#pragma unroll
        for (int ni = 0; ni < 4; ni++) {
            int row = m0 + wm * 32 + mi * 16 + er;
            int col = n0 + wn * 32 + ni * 8 + ec;
            float* cp0 = C + (size_t)row * EMBED + col;
            float* cp1 = C + (size_t)(row + 8) * EMBED + col;
            *(float2*)cp0 = make_float2(acc[mi][ni][0], acc[mi][ni][1]);
            *(float2*)cp1 = make_float2(acc[mi][ni][2], acc[mi][ni][3]);
        }
    }
}

__global__ __launch_bounds__(512, 1) void qkv_tc_kernel(
    const float* __restrict__ x,
    const float* __restrict__ Wq, const float* __restrict__ Wk,
    const float* __restrict__ Wv)
{
    const float* B;
    float* C;
    if (blockIdx.z == 0)      { B = Wq; C = g_q; }
    else if (blockIdx.z == 1) { B = Wk; C = g_k; }
    else                      { B = Wv; C = g_v; }
    gemm_tc_body(x, B, C);
}

__global__ __launch_bounds__(512, 1) void out_tc_kernel(
    const float* __restrict__ Wo, float* __restrict__ out)
{
    gemm_tc_body(g_a, Wo, out);
}

// ===========================================================================
// Tensor-core flash attention (split-bf16), 512 threads = 16 warps.
// CTA: 256 query rows of one (b,h). K/V chunks of 64 keys,
// DOUBLE-BUFFERED with register prefetch; single barrier per chunk.
// ===========================================================================
#define LQE 72                        // padded row stride (bf16 elems), 144 B
#define QTILE (256 * LQE * 2)         // 36864 B
#define KTILE (64 * LQE * 2)          // 9216 B
#define KVSTAGE (4 * KTILE)           // Kh,Kl,Vh,Vl = 36864 B per stage
#define AQH 0
#define AQL QTILE
#define AKV (2 * QTILE)               // two stages follow
#define SMEM_ATTN (2 * QTILE + 2 * KVSTAGE)   // 147456 B

__global__ __launch_bounds__(512, 1) void attn_tc_kernel(
    const float* __restrict__ qw)
{
    extern __shared__ char smem[];
    const uint32_t sb = smem_u32(smem);
    const int tid  = threadIdx.x;
    const int lane = tid & 31;
    const int w    = tid >> 5;
    const int h = blockIdx.y;
    const int b = blockIdx.z;
    const int q0 = blockIdx.x * 256;

    const size_t base = (size_t)b * SEQ * EMBED + (size_t)h * DK;

    // ---- load Q tile (256x64), scale by 1/8, split hi/lo into SMEM ----
    {
        const float* Qg = g_q + base + (size_t)q0 * EMBED;
#pragma unroll
        for (int i = 0; i < 8; i++) {
            int idx = i * 512 + tid;
            int row = idx >> 4, col = idx & 15;
            float4 v = *(const float4*)(Qg + (size_t)row * EMBED + col * 4);
            v.x *= 0.125f; v.y *= 0.125f; v.z *= 0.125f; v.w *= 0.125f;
            uint2 hh, ll;
            cvt_split4(v, hh, ll);
            uint32_t bo = row * (LQE * 2) + col * 8;
            *(uint2*)(smem + AQH + bo) = hh;
            *(uint2*)(smem + AQL + bo) = ll;
        }
    }
    __syncthreads();

    // ---- Q fragments (A operand), register resident ----
    uint32_t qh[4][4], ql[4][4];
    {
        const uint32_t aoff = (uint32_t)(w * 16 + (lane & 15)) * (LQE * 2) + (lane >> 4) * 16;
#pragma unroll
        for (int ks = 0; ks < 4; ks++) {
            ldm_x4(qh[ks], sb + AQH + aoff + ks * 32);
            ldm_x4(ql[ks], sb + AQL + aoff + ks * 32);
        }
    }

    float O[8][4];
#pragma unroll
    for (int i = 0; i < 8; i++)
#pragma unroll
        for (int j = 0; j < 4; j++) O[i][j] = 0.0f;
    float M0 = -1e30f, M1 = -1e30f, L0 = 0.0f, L1 = 0.0f;

    const uint32_t kb_row = ((lane >> 4) & 1) * 8 + (lane & 7);
    const uint32_t kb_kb  = ((lane >> 3) & 1) * 16;
    const uint32_t vb_row = ((lane >> 3) & 1) * 8 + (lane & 7);
    const uint32_t vb_nb  = (lane >> 4) * 16;

    // per-thread K/V load slots: 64x16 float4 = 1024 / 512 threads = 2 each
    int krow[2], kf4[2];
#pragma unroll
    for (int i = 0; i < 2; i++) {
        int idx = i * 512 + tid;
        krow[i] = idx >> 4;
        kf4[i]  = idx & 15;
    }

    // prefetch chunk 0
    float4 pk[2], pv[2];
    {
        const float* Kg = g_k + base;
        const float* Vg = g_v + base;
#pragma unroll
        for (int i = 0; i < 2; i++) {
            pk[i] = *(const float4*)(Kg + (size_t)krow[i] * EMBED + kf4[i] * 4);
            pv[i] = *(const float4*)(Vg + (size_t)krow[i] * EMBED + kf4[i] * 4);
        }
    }

    const int NCH = SEQ / 64;   // 32
    for (int c = 0; c < NCH; ++c) {
        const int p = c & 1;
        char* st = smem + AKV + p * KVSTAGE;

        // store prefetched K/V (split hi/lo) into stage p
#pragma unroll
        for (int i = 0; i < 2; i++) {
            uint32_t bo = krow[i] * (LQE * 2) + kf4[i] * 8;
            uint2 hh, ll;
            cvt_split4(pk[i], hh, ll);
            *(uint2*)(st + 0 * KTILE + bo) = hh;
            *(uint2*)(st + 1 * KTILE + bo) = ll;
            cvt_split4(pv[i], hh, ll);
            *(uint2*)(st + 2 * KTILE + bo) = hh;
            *(uint2*)(st + 3 * KTILE + bo) = ll;
        }
        __syncthreads();   // single barrier per chunk

        // prefetch next chunk (overlaps compute)
        if (c + 1 < NCH) {
            const float* Kg = g_k + base + (size_t)(c + 1) * 64 * EMBED;
            const float* Vg = g_v + base + (size_t)(c + 1) * 64 * EMBED;
#pragma unroll
            for (int i = 0; i < 2; i++) {
                pk[i] = *(const float4*)(Kg + (size_t)krow[i] * EMBED + kf4[i] * 4);
                pv[i] = *(const float4*)(Vg + (size_t)krow[i] * EMBED + kf4[i] * 4);
            }
        }

        const uint32_t sKh = sb + AKV + p * KVSTAGE;
        const uint32_t sKl = sKh + KTILE;
        const uint32_t sVh = sKh + 2 * KTILE;
        const uint32_t sVl = sKh + 3 * KTILE;

        // ---- scores: s[8][4] = (Q/8) . K^T (64 keys) ----
        float s[8][4];
#pragma unroll
        for (int i = 0; i < 8; i++)
#pragma unroll
            for (int j = 0; j < 4; j++) s[i][j] = 0.0f;

#pragma unroll
        for (int ks = 0; ks < 4; ks++) {
#pragma unroll
            for (int kp = 0; kp < 4; kp++) {
                uint32_t ro = (uint32_t)(kp * 16 + kb_row) * (LQE * 2) + kb_kb + ks * 32;
                uint32_t rh[4], rl[4];
                ldm_x4(rh, sKh + ro);
                ldm_x4(rl, sKl + ro);
                uint32_t bh0[2] = { rh[0], rh[1] }, bh1[2] = { rh[2], rh[3] };
                uint32_t bl0[2] = { rl[0], rl[1] }, bl1[2] = { rl[2], rl[3] };
                mma16816(s[2 * kp],     qh[ks], bh0);
                mma16816(s[2 * kp],     qh[ks], bl0);
                mma16816(s[2 * kp],     ql[ks], bh0);
                mma16816(s[2 * kp + 1], qh[ks], bh1);
                mma16816(s[2 * kp + 1], qh[ks], bl1);
                mma16816(s[2 * kp + 1], ql[ks], bh1);
            }
        }

        // ---- online softmax ----
        float rm0 = -1e30f, rm1 = -1e30f;
#pragma unroll
        for (int i = 0; i < 8; i++) {
            rm0 = fmaxf(rm0, fmaxf(s[i][0], s[i][1]));
            rm1 = fmaxf(rm1, fmaxf(s[i][2], s[i][3]));
        }
        rm0 = fmaxf(rm0, __shfl_xor_sync(0xFFFFFFFF, rm0, 1));
        rm0 = fmaxf(rm0, __shfl_xor_sync(0xFFFFFFFF, rm0, 2));
        rm1 = fmaxf(rm1, __shfl_xor_sync(0xFFFFFFFF, rm1, 1));
        rm1 = fmaxf(rm1, __shfl_xor_sync(0xFFFFFFFF, rm1, 2));

        float Mn0 = fmaxf(M0, rm0), Mn1 = fmaxf(M1, rm1);
        float sc0 = __expf(M0 - Mn0), sc1 = __expf(M1 - Mn1);
        M0 = Mn0; M1 = Mn1;
        L0 *= sc0; L1 *= sc1;
#pragma unroll
        for (int i = 0; i < 8; i++) {
            O[i][0] *= sc0; O[i][1] *= sc0;
            O[i][2] *= sc1; O[i][3] *= sc1;
        }
#pragma unroll
        for (int i = 0; i < 8; i++) {
            s[i][0] = __expf(s[i][0] - M0);
            s[i][1] = __expf(s[i][1] - M0);
            s[i][2] = __expf(s[i][2] - M1);
            s[i][3] = __expf(s[i][3] - M1);
            L0 += s[i][0] + s[i][1];
            L1 += s[i][2] + s[i][3];
        }

        // ---- O += P . V ----
#pragma unroll
        for (int ks = 0; ks < 4; ks++) {
            uint32_t ph[4], pl[4];
            cvt_split2(s[2 * ks][0],     s[2 * ks][1],     ph[0], pl[0]);
            cvt_split2(s[2 * ks][2],     s[2 * ks][3],     ph[1], pl[1]);
            cvt_split2(s[2 * ks + 1][0], s[2 * ks + 1][1], ph[2], pl[2]);
            cvt_split2(s[2 * ks + 1][2], s[2 * ks + 1][3], ph[3], pl[3]);

            const uint32_t vro = (uint32_t)(ks * 16 + vb_row) * (LQE * 2) + vb_nb;
#pragma unroll
            for (int ntp = 0; ntp < 4; ntp++) {
                uint32_t rh[4], rl[4];
                ldm_x4_t(rh, sVh + vro + ntp * 32);
                ldm_x4_t(rl, sVl + vro + ntp * 32);
                uint32_t vh0[2] = { rh[0], rh[1] }, vh1[2] = { rh[2], rh[3] };
                uint32_t vl0[2] = { rl[0], rl[1] }, vl1[2] = { rl[2], rl[3] };
                mma16816(O[2 * ntp],     ph, vh0);
                mma16816(O[2 * ntp],     ph, vl0);
                mma16816(O[2 * ntp],     pl, vh0);
                mma16816(O[2 * ntp + 1], ph, vh1);
                mma16816(O[2 * ntp + 1], ph, vl1);
                mma16816(O[2 * ntp + 1], pl, vh1);
            }
        }
    }

    // ---- finalize: reduce L, normalize, sin-mix, write ----
    L0 += __shfl_xor_sync(0xFFFFFFFF, L0, 1);
    L0 += __shfl_xor_sync(0xFFFFFFFF, L0, 2);
    L1 += __shfl_xor_sync(0xFFFFFFFF, L1, 1);
    L1 += __shfl_xor_sync(0xFFFFFFFF, L1, 2);
    const float inv0 = 1.0f / L0, inv1 = 1.0f / L1;
    const float wmix = 1.0f / (1.0f + __expf(-qw[h]));

    const int r0 = q0 + w * 16 + (lane >> 2);
    const int c0 = (lane & 3) * 2;
    float* out0 = g_a + base + (size_t)r0 * EMBED + c0;
    float* out1 = g_a + base + (size_t)(r0 + 8) * EMBED + c0;
#pragma unroll
    for (int nt = 0; nt < 8; nt++) {
        float ca = O[nt][0] * inv0, cb = O[nt][1] * inv0;
        float cc = O[nt][2] * inv1, cd = O[nt][3] * inv1;
        *(float2*)(out0 + nt * 8) = make_float2(
            wmix * sinf(ca) + (1.0f - wmix) * ca,
            wmix * sinf(cb) + (1.0f - wmix) * cb);
        *(float2*)(out1 + nt * 8) = make_float2(
            wmix * sinf(cc) + (1.0f - wmix) * cc,
            wmix * sinf(cd) + (1.0f - wmix) * cd);
    }
}

// ---------------------------------------------------------------------------
extern "C" void kernel_launch(void* const* d_in, const int* in_sizes, int n_in,
                              void* d_out, int out_size)
{
    const float* x  = (const float*)d_in[0];
    const float* Wq = (const float*)d_in[1];
    const float* Wk = (const float*)d_in[2];
    const float* Wv = (const float*)d_in[3];
    const float* Wo = (const float*)d_in[4];
    const float* qw = (const float*)d_in[5];
    float* out = (float*)d_out;

    const int M = in_sizes[0] / EMBED;   // B*S = 4096
    const int S = SEQ;
    const int B = M / S;

    static bool attr_done = false;
    if (!attr_done) {
        cudaFuncSetAttribute(qkv_tc_kernel, cudaFuncAttributeMaxDynamicSharedMemorySize, SMEM_GEMM);
        cudaFuncSetAttribute(out_tc_kernel, cudaFuncAttributeMaxDynamicSharedMemorySize, SMEM_GEMM);
        cudaFuncSetAttribute(attn_tc_kernel, cudaFuncAttributeMaxDynamicSharedMemorySize, SMEM_ATTN);
        attr_done = true;
    }

    // 1) Q,K,V projections
    {
        dim3 grid(EMBED / TN, M / TM, 3);
        qkv_tc_kernel<<<grid, 512, SMEM_GEMM>>>(x, Wq, Wk, Wv);
    }
    // 2) Tensor-core flash attention + mix epilogue (double-buffered K/V)
    {
        dim3 grid(S / 256, HEADS, B);
        attn_tc_kernel<<<grid, 512, SMEM_ATTN>>>(qw);
    }
    // 3) Output projection
    {
        dim3 grid(EMBED / TN, M / TM, 1);
        out_tc_kernel<<<grid, 512, SMEM_GEMM>>>(Wo, out);
    }
}

// round 8
// speedup vs baseline: 3.3750x; 1.1198x over previous
#include <cuda_runtime.h>
#include <cuda_bf16.h>
#include <math.h>
#include <stdint.h>

#define EMBED 1024
#define HEADS 16
#define DK 64
#define SEQ 2048
#define MAXM 4096
#define NELEM (MAXM * EMBED)

// Persistent split-bf16 scratch (allocation-free rule: __device__ globals)
__device__ __nv_bfloat16 g_xh[NELEM], g_xl[NELEM];
__device__ __nv_bfloat16 g_wh[4 * EMBED * EMBED], g_wl[4 * EMBED * EMBED];
__device__ __nv_bfloat16 g_qh[NELEM], g_ql[NELEM];
__device__ __nv_bfloat16 g_kh[NELEM], g_kl[NELEM];
__device__ __nv_bfloat16 g_vh[NELEM], g_vl[NELEM];
__device__ __nv_bfloat16 g_ah[NELEM], g_al[NELEM];

// ===========================================================================
// Common helpers
// ===========================================================================
__device__ __forceinline__ uint32_t smem_u32(const void* p) {
    uint32_t a;
    asm("{ .reg .u64 t; cvta.to.shared.u64 t, %1; cvt.u32.u64 %0, t; }"
        : "=r"(a) : "l"(p));
    return a;
}

__device__ __forceinline__ void ldm_x4(uint32_t* r, uint32_t addr) {
    asm volatile("ldmatrix.sync.aligned.m8n8.x4.shared.b16 {%0,%1,%2,%3}, [%4];"
                 : "=r"(r[0]), "=r"(r[1]), "=r"(r[2]), "=r"(r[3]) : "r"(addr));
}

__device__ __forceinline__ void ldm_x4_t(uint32_t* r, uint32_t addr) {
    asm volatile("ldmatrix.sync.aligned.m8n8.x4.trans.shared.b16 {%0,%1,%2,%3}, [%4];"
                 : "=r"(r[0]), "=r"(r[1]), "=r"(r[2]), "=r"(r[3]) : "r"(addr));
}

__device__ __forceinline__ void mma16816(float* d, const uint32_t* a, const uint32_t* b) {
    asm volatile(
        "mma.sync.aligned.m16n8k16.row.col.f32.bf16.bf16.f32 "
        "{%0,%1,%2,%3}, {%4,%5,%6,%7}, {%8,%9}, {%0,%1,%2,%3};"
        : "+f"(d[0]), "+f"(d[1]), "+f"(d[2]), "+f"(d[3])
        : "r"(a[0]), "r"(a[1]), "r"(a[2]), "r"(a[3]), "r"(b[0]), "r"(b[1]));
}

__device__ __forceinline__ uint32_t packbf(__nv_bfloat16 a, __nv_bfloat16 b) {
    return (uint32_t)__bfloat16_as_ushort(a) | ((uint32_t)__bfloat16_as_ushort(b) << 16);
}

__device__ __forceinline__ void cvt_split4(float4 v, uint2& h, uint2& l) {
    __nv_bfloat16 h0 = __float2bfloat16(v.x);
    __nv_bfloat16 h1 = __float2bfloat16(v.y);
    __nv_bfloat16 h2 = __float2bfloat16(v.z);
    __nv_bfloat16 h3 = __float2bfloat16(v.w);
    __nv_bfloat16 l0 = __float2bfloat16(v.x - __bfloat162float(h0));
    __nv_bfloat16 l1 = __float2bfloat16(v.y - __bfloat162float(h1));
    __nv_bfloat16 l2 = __float2bfloat16(v.z - __bfloat162float(h2));
    __nv_bfloat16 l3 = __float2bfloat16(v.w - __bfloat162float(h3));
    h.x = packbf(h0, h1); h.y = packbf(h2, h3);
    l.x = packbf(l0, l1); l.y = packbf(l2, l3);
}

__device__ __forceinline__ void cvt_split2(float a, float b, uint32_t& h, uint32_t& l) {
    __nv_bfloat16 h0 = __float2bfloat16(a);
    __nv_bfloat16 h1 = __float2bfloat16(b);
    h = packbf(h0, h1);
    l = packbf(__float2bfloat16(a - __bfloat162float(h0)),
               __float2bfloat16(b - __bfloat162float(h1)));
}

// ===========================================================================
// Prep: split fp32 -> (hi, lo) bf16, vectorized
// ===========================================================================
__global__ __launch_bounds__(256) void split_fp32_kernel(
    const float4* __restrict__ src, uint2* __restrict__ hi, uint2* __restrict__ lo, int n4)
{
    int i = blockIdx.x * blockDim.x + threadIdx.x;
    if (i < n4) {
        uint2 h, l;
        cvt_split4(src[i], h, l);
        hi[i] = h;
        lo[i] = l;
    }
}

// ===========================================================================
// GEMM on pre-split bf16:  C[m,n] = sum_k A[m,k]*B[n,k]  (NT)
// CTA 128x128, 512 threads (16 warps 4x4, warp tile 32x32), K-chunk 64.
// 2-stage SMEM double buffer, single barrier per chunk.
// ===========================================================================
#define TM 128
#define TN 128
#define KCH 64
#define LDB 144                  // padded row stride in bytes (64 bf16 + 8 pad)
#define GT (128 * LDB)           // 18432 per 128x64 tile
#define GSTAGE (4 * GT)          // Ah Al Bh Bl
#define SMEM_GEMM (2 * GSTAGE)   // 147456

template <int SPLIT_OUT>
__device__ __forceinline__ void gemm_bf16_body(
    const __nv_bfloat16* __restrict__ Ah, const __nv_bfloat16* __restrict__ Al,
    const __nv_bfloat16* __restrict__ Bh, const __nv_bfloat16* __restrict__ Bl,
    float* __restrict__ Cf,
    __nv_bfloat16* __restrict__ Ch, __nv_bfloat16* __restrict__ Cl,
    float scale)
{
    extern __shared__ char smem[];
    const uint32_t sbase = smem_u32(smem);
    const int tid  = threadIdx.x;
    const int lane = tid & 31;
    const int wid  = tid >> 5;
    const int wm   = wid & 3;
    const int wn   = wid >> 2;
    const int m0 = blockIdx.y * TM;
    const int n0 = blockIdx.x * TN;

    float acc[2][4][4];
#pragma unroll
    for (int i = 0; i < 2; i++)
#pragma unroll
        for (int j = 0; j < 4; j++)
#pragma unroll
            for (int r = 0; r < 4; r++) acc[i][j][r] = 0.0f;

    // load slots: 128 rows x 8 uint4 per tile = 1024 / 512 threads = 2 each
    int lrow[2], lu4[2];
#pragma unroll
    for (int i = 0; i < 2; i++) {
        int idx = tid + i * 512;
        lrow[i] = idx >> 3;
        lu4[i]  = idx & 7;
    }

    const __nv_bfloat16* Abh = Ah + (size_t)m0 * EMBED;
    const __nv_bfloat16* Abl = Al + (size_t)m0 * EMBED;
    const __nv_bfloat16* Bbh = Bh + (size_t)n0 * EMBED;
    const __nv_bfloat16* Bbl = Bl + (size_t)n0 * EMBED;

    uint4 pah[2], pal[2], pbh[2], pbl[2];
#pragma unroll
    for (int i = 0; i < 2; i++) {
        size_t off = (size_t)lrow[i] * EMBED + lu4[i] * 8;
        pah[i] = *(const uint4*)(Abh + off);
        pal[i] = *(const uint4*)(Abl + off);
        pbh[i] = *(const uint4*)(Bbh + off);
        pbl[i] = *(const uint4*)(Bbl + off);
    }

    const int a_row = wm * 32 + (lane & 15);
    const int a_kb  = (lane >> 4) * 16;
    const int b_row = wn * 32 + ((lane >> 4) & 1) * 8 + (lane & 7);
    const int b_kb  = ((lane >> 3) & 1) * 16;

    const int NCHUNK = EMBED / KCH;   // 16
    for (int c = 0; c < NCHUNK; ++c) {
        const int p = c & 1;
        char* st = smem + p * GSTAGE;

#pragma unroll
        for (int i = 0; i < 2; i++) {
            uint32_t bo = lrow[i] * LDB + lu4[i] * 16;
            *(uint4*)(st + 0 * GT + bo) = pah[i];
            *(uint4*)(st + 1 * GT + bo) = pal[i];
            *(uint4*)(st + 2 * GT + bo) = pbh[i];
            *(uint4*)(st + 3 * GT + bo) = pbl[i];
        }
        __syncthreads();   // single barrier per chunk (2-stage buffer)

        if (c + 1 < NCHUNK) {
            const int koff = (c + 1) * KCH;
#pragma unroll
            for (int i = 0; i < 2; i++) {
                size_t off = (size_t)lrow[i] * EMBED + koff + lu4[i] * 8;
                pah[i] = *(const uint4*)(Abh + off);
                pal[i] = *(const uint4*)(Abl + off);
                pbh[i] = *(const uint4*)(Bbh + off);
                pbl[i] = *(const uint4*)(Bbl + off);
            }
        }

        const uint32_t sAh = sbase + p * GSTAGE;
        const uint32_t sAl = sAh + GT;
        const uint32_t sBh = sAh + 2 * GT;
        const uint32_t sBl = sAh + 3 * GT;

#pragma unroll
        for (int ks = 0; ks < 4; ++ks) {
            uint32_t ah[2][4], al[2][4];
            uint32_t bh[4][2], bl[4][2];

            const uint32_t akoff = ks * 32 + a_kb;
#pragma unroll
            for (int mi = 0; mi < 2; mi++) {
                uint32_t ro = (uint32_t)(a_row + mi * 16) * LDB + akoff;
                ldm_x4(ah[mi], sAh + ro);
                ldm_x4(al[mi], sAl + ro);
            }
            const uint32_t bkoff = ks * 32 + b_kb;
#pragma unroll
            for (int np = 0; np < 2; np++) {
                uint32_t ro = (uint32_t)(b_row + np * 16) * LDB + bkoff;
                uint32_t r[4];
                ldm_x4(r, sBh + ro);
                bh[np * 2][0] = r[0]; bh[np * 2][1] = r[1];
                bh[np * 2 + 1][0] = r[2]; bh[np * 2 + 1][1] = r[3];
                ldm_x4(r, sBl + ro);
                bl[np * 2][0] = r[0]; bl[np * 2][1] = r[1];
                bl[np * 2 + 1][0] = r[2]; bl[np * 2 + 1][1] = r[3];
            }

#pragma unroll
            for (int mi = 0; mi < 2; mi++)
#pragma unroll
                for (int ni = 0; ni < 4; ni++) {
                    mma16816(acc[mi][ni], ah[mi], bh[ni]);
                    mma16816(acc[mi][ni], ah[mi], bl[ni]);
                    mma16816(acc[mi][ni], al[mi], bh[ni]);
                }
        }
    }

    const int er = lane >> 2;
    const int ec = (lane & 3) * 2;
#pragma unroll
    for (int mi = 0; mi < 2; mi++) {
#pragma unroll
        for (int ni = 0; ni < 4; ni++) {
            int row = m0 + wm * 32 + mi * 16 + er;
            int col = n0 + wn * 32 + ni * 8 + ec;
            if (SPLIT_OUT) {
                float a0 = acc[mi][ni][0] * scale, a1 = acc[mi][ni][1] * scale;
                float a2 = acc[mi][ni][2] * scale, a3 = acc[mi][ni][3] * scale;
                uint32_t h, l;
                cvt_split2(a0, a1, h, l);
                *(uint32_t*)(Ch + (size_t)row * EMBED + col) = h;
                *(uint32_t*)(Cl + (size_t)row * EMBED + col) = l;
                cvt_split2(a2, a3, h, l);
                *(uint32_t*)(Ch + (size_t)(row + 8) * EMBED + col) = h;
                *(uint32_t*)(Cl + (size_t)(row + 8) * EMBED + col) = l;
            } else {
                *(float2*)(Cf + (size_t)row * EMBED + col) =
                    make_float2(acc[mi][ni][0], acc[mi][ni][1]);
                *(float2*)(Cf + (size_t)(row + 8) * EMBED + col) =
                    make_float2(acc[mi][ni][2], acc[mi][ni][3]);
            }
        }
    }
}

__global__ __launch_bounds__(512, 1) void qkv_tc_kernel()
{
    const int z = blockIdx.z;
    const __nv_bfloat16* Bh = g_wh + (size_t)z * EMBED * EMBED;
    const __nv_bfloat16* Bl = g_wl + (size_t)z * EMBED * EMBED;
    __nv_bfloat16 *Ch, *Cl;
    float scale;
    if (z == 0)      { Ch = g_qh; Cl = g_ql; scale = 0.125f; }  // fold 1/sqrt(DK)
    else if (z == 1) { Ch = g_kh; Cl = g_kl; scale = 1.0f; }
    else             { Ch = g_vh; Cl = g_vl; scale = 1.0f; }
    gemm_bf16_body<1>(g_xh, g_xl, Bh, Bl, nullptr, Ch, Cl, scale);
}

__global__ __launch_bounds__(512, 1) void out_tc_kernel(float* __restrict__ out)
{
    gemm_bf16_body<0>(g_ah, g_al,
                      g_wh + (size_t)3 * EMBED * EMBED, g_wl + (size_t)3 * EMBED * EMBED,
                      out, nullptr, nullptr, 1.0f);
}

// ===========================================================================
// Tensor-core flash attention on pre-split bf16 q/k/v.
// 512 threads = 16 warps; CTA = 256 query rows; 64-key chunks, double buffer.
// ===========================================================================
#define KT (64 * LDB)                 // 9216
#define QT (256 * LDB)                // 36864
#define AQH 0
#define AQL QT
#define AKV (2 * QT)
#define KVST (4 * KT)                 // Kh Kl Vh Vl per stage
#define SMEM_ATTN (2 * QT + 2 * KVST) // 147456

__global__ __launch_bounds__(512, 1) void attn_tc_kernel(
    const float* __restrict__ qw)
{
    extern __shared__ char smem[];
    const uint32_t sb = smem_u32(smem);
    const int tid  = threadIdx.x;
    const int lane = tid & 31;
    const int w    = tid >> 5;
    const int h = blockIdx.y;
    const int b = blockIdx.z;
    const int q0 = blockIdx.x * 256;

    const size_t base = (size_t)b * SEQ * EMBED + (size_t)h * DK;

    // ---- copy pre-split Q tile (256x64 bf16 hi+lo) into SMEM ----
    {
        const __nv_bfloat16* Qh = g_qh + base + (size_t)q0 * EMBED;
        const __nv_bfloat16* Ql = g_ql + base + (size_t)q0 * EMBED;
#pragma unroll
        for (int i = 0; i < 4; i++) {
            int idx = i * 512 + tid;          // 0..2047
            int row = idx >> 3, u4 = idx & 7;
            size_t off = (size_t)row * EMBED + u4 * 8;
            uint32_t bo = row * LDB + u4 * 16;
            *(uint4*)(smem + AQH + bo) = *(const uint4*)(Qh + off);
            *(uint4*)(smem + AQL + bo) = *(const uint4*)(Ql + off);
        }
    }
    __syncthreads();

    // ---- Q fragments, register resident ----
    uint32_t qh[4][4], ql[4][4];
    {
        const uint32_t aoff = (uint32_t)(w * 16 + (lane & 15)) * LDB + (lane >> 4) * 16;
#pragma unroll
        for (int ks = 0; ks < 4; ks++) {
            ldm_x4(qh[ks], sb + AQH + aoff + ks * 32);
            ldm_x4(ql[ks], sb + AQL + aoff + ks * 32);
        }
    }

    float O[8][4];
#pragma unroll
    for (int i = 0; i < 8; i++)
#pragma unroll
        for (int j = 0; j < 4; j++) O[i][j] = 0.0f;
    float M0 = -1e30f, M1 = -1e30f, L0 = 0.0f, L1 = 0.0f;

    const uint32_t kb_row = ((lane >> 4) & 1) * 8 + (lane & 7);
    const uint32_t kb_kb  = ((lane >> 3) & 1) * 16;
    const uint32_t vb_row = ((lane >> 3) & 1) * 8 + (lane & 7);
    const uint32_t vb_nb  = (lane >> 4) * 16;

    // K/V slots: 64 rows x 8 uint4 = 512 per tile / 512 threads = 1 each
    const int krow = tid >> 3;
    const int ku4  = tid & 7;

    uint4 pkh, pkl, pvh, pvl;
    {
        size_t off = base + (size_t)krow * EMBED + ku4 * 8;
        pkh = *(const uint4*)(g_kh + off);
        pkl = *(const uint4*)(g_kl + off);
        pvh = *(const uint4*)(g_vh + off);
        pvl = *(const uint4*)(g_vl + off);
    }

    const int NCH = SEQ / 64;   // 32
    for (int c = 0; c < NCH; ++c) {
        const int p = c & 1;
        char* st = smem + AKV + p * KVST;

        {
            uint32_t bo = krow * LDB + ku4 * 16;
            *(uint4*)(st + 0 * KT + bo) = pkh;
            *(uint4*)(st + 1 * KT + bo) = pkl;
            *(uint4*)(st + 2 * KT + bo) = pvh;
            *(uint4*)(st + 3 * KT + bo) = pvl;
        }
        __syncthreads();   // single barrier per chunk

        if (c + 1 < NCH) {
            size_t off = base + (size_t)((c + 1) * 64 + krow) * EMBED + ku4 * 8;
            pkh = *(const uint4*)(g_kh + off);
            pkl = *(const uint4*)(g_kl + off);
            pvh = *(const uint4*)(g_vh + off);
            pvl = *(const uint4*)(g_vl + off);
        }

        const uint32_t sKh = sb + AKV + p * KVST;
        const uint32_t sKl = sKh + KT;
        const uint32_t sVh = sKh + 2 * KT;
        const uint32_t sVl = sKh + 3 * KT;

        // ---- scores (Q pre-scaled by 1/8 at projection) ----
        float s[8][4];
#pragma unroll
        for (int i = 0; i < 8; i++)
#pragma unroll
            for (int j = 0; j < 4; j++) s[i][j] = 0.0f;

#pragma unroll
        for (int ks = 0; ks < 4; ks++) {
#pragma unroll
            for (int kp = 0; kp < 4; kp++) {
                uint32_t ro = (uint32_t)(kp * 16 + kb_row) * LDB + kb_kb + ks * 32;
                uint32_t rh[4], rl[4];
                ldm_x4(rh, sKh + ro);
                ldm_x4(rl, sKl + ro);
                uint32_t bh0[2] = { rh[0], rh[1] }, bh1[2] = { rh[2], rh[3] };
                uint32_t bl0[2] = { rl[0], rl[1] }, bl1[2] = { rl[2], rl[3] };
                mma16816(s[2 * kp],     qh[ks], bh0);
                mma16816(s[2 * kp],     qh[ks], bl0);
                mma16816(s[2 * kp],     ql[ks], bh0);
                mma16816(s[2 * kp + 1], qh[ks], bh1);
                mma16816(s[2 * kp + 1], qh[ks], bl1);
                mma16816(s[2 * kp + 1], ql[ks], bh1);
            }
        }

        // ---- online softmax ----
        float rm0 = -1e30f, rm1 = -1e30f;
#pragma unroll
        for (int i = 0; i < 8; i++) {
            rm0 = fmaxf(rm0, fmaxf(s[i][0], s[i][1]));
            rm1 = fmaxf(rm1, fmaxf(s[i][2], s[i][3]));
        }
        rm0 = fmaxf(rm0, __shfl_xor_sync(0xFFFFFFFF, rm0, 1));
        rm0 = fmaxf(rm0, __shfl_xor_sync(0xFFFFFFFF, rm0, 2));
        rm1 = fmaxf(rm1, __shfl_xor_sync(0xFFFFFFFF, rm1, 1));
        rm1 = fmaxf(rm1, __shfl_xor_sync(0xFFFFFFFF, rm1, 2));

        float Mn0 = fmaxf(M0, rm0), Mn1 = fmaxf(M1, rm1);
        float sc0 = __expf(M0 - Mn0), sc1 = __expf(M1 - Mn1);
        M0 = Mn0; M1 = Mn1;
        L0 *= sc0; L1 *= sc1;
#pragma unroll
        for (int i = 0; i < 8; i++) {
            O[i][0] *= sc0; O[i][1] *= sc0;
            O[i][2] *= sc1; O[i][3] *= sc1;
        }
#pragma unroll
        for (int i = 0; i < 8; i++) {
            s[i][0] = __expf(s[i][0] - M0);
            s[i][1] = __expf(s[i][1] - M0);
            s[i][2] = __expf(s[i][2] - M1);
            s[i][3] = __expf(s[i][3] - M1);
            L0 += s[i][0] + s[i][1];
            L1 += s[i][2] + s[i][3];
        }

        // ---- O += P . V ----
#pragma unroll
        for (int ks = 0; ks < 4; ks++) {
            uint32_t ph[4], pl[4];
            cvt_split2(s[2 * ks][0],     s[2 * ks][1],     ph[0], pl[0]);
            cvt_split2(s[2 * ks][2],     s[2 * ks][3],     ph[1], pl[1]);
            cvt_split2(s[2 * ks + 1][0], s[2 * ks + 1][1], ph[2], pl[2]);
            cvt_split2(s[2 * ks + 1][2], s[2 * ks + 1][3], ph[3], pl[3]);

            const uint32_t vro = (uint32_t)(ks * 16 + vb_row) * LDB + vb_nb;
#pragma unroll
            for (int ntp = 0; ntp < 4; ntp++) {
                uint32_t rh[4], rl[4];
                ldm_x4_t(rh, sVh + vro + ntp * 32);
                ldm_x4_t(rl, sVl + vro + ntp * 32);
                uint32_t vh0[2] = { rh[0], rh[1] }, vh1[2] = { rh[2], rh[3] };
                uint32_t vl0[2] = { rl[0], rl[1] }, vl1[2] = { rl[2], rl[3] };
                mma16816(O[2 * ntp],     ph, vh0);
                mma16816(O[2 * ntp],     ph, vl0);
                mma16816(O[2 * ntp],     pl, vh0);
                mma16816(O[2 * ntp + 1], ph, vh1);
                mma16816(O[2 * ntp + 1], ph, vl1);
                mma16816(O[2 * ntp + 1], pl, vh1);
            }
        }
    }

    // ---- finalize: normalize, sin-mix, write split bf16 ----
    L0 += __shfl_xor_sync(0xFFFFFFFF, L0, 1);
    L0 += __shfl_xor_sync(0xFFFFFFFF, L0, 2);
    L1 += __shfl_xor_sync(0xFFFFFFFF, L1, 1);
    L1 += __shfl_xor_sync(0xFFFFFFFF, L1, 2);
    const float inv0 = 1.0f / L0, inv1 = 1.0f / L1;
    const float wmix = 1.0f / (1.0f + __expf(-qw[h]));

    const int r0 = q0 + w * 16 + (lane >> 2);
    const int c0 = (lane & 3) * 2;
    __nv_bfloat16* oh0 = g_ah + base + (size_t)r0 * EMBED + c0;
    __nv_bfloat16* ol0 = g_al + base + (size_t)r0 * EMBED + c0;
    __nv_bfloat16* oh1 = g_ah + base + (size_t)(r0 + 8) * EMBED + c0;
    __nv_bfloat16* ol1 = g_al + base + (size_t)(r0 + 8) * EMBED + c0;
#pragma unroll
    for (int nt = 0; nt < 8; nt++) {
        float ca = O[nt][0] * inv0, cb = O[nt][1] * inv0;
        float cc = O[nt][2] * inv1, cd = O[nt][3] * inv1;
        float ma = wmix * sinf(ca) + (1.0f - wmix) * ca;
        float mb = wmix * sinf(cb) + (1.0f - wmix) * cb;
        float mc = wmix * sinf(cc) + (1.0f - wmix) * cc;
        float md = wmix * sinf(cd) + (1.0f - wmix) * cd;
        uint32_t hh, ll;
        cvt_split2(ma, mb, hh, ll);
        *(uint32_t*)(oh0 + nt * 8) = hh;
        *(uint32_t*)(ol0 + nt * 8) = ll;
        cvt_split2(mc, md, hh, ll);
        *(uint32_t*)(oh1 + nt * 8) = hh;
        *(uint32_t*)(ol1 + nt * 8) = ll;
    }
}

// ---------------------------------------------------------------------------
extern "C" void kernel_launch(void* const* d_in, const int* in_sizes, int n_in,
                              void* d_out, int out_size)
{
    const float* x  = (const float*)d_in[0];
    const float* Wq = (const float*)d_in[1];
    const float* Wk = (const float*)d_in[2];
    const float* Wv = (const float*)d_in[3];
    const float* Wo = (const float*)d_in[4];
    const float* qw = (const float*)d_in[5];
    float* out = (float*)d_out;

    const int M = in_sizes[0] / EMBED;   // B*S = 4096
    const int S = SEQ;
    const int B = M / S;

    static bool attr_done = false;
    if (!attr_done) {
        cudaFuncSetAttribute(qkv_tc_kernel, cudaFuncAttributeMaxDynamicSharedMemorySize, SMEM_GEMM);
        cudaFuncSetAttribute(out_tc_kernel, cudaFuncAttributeMaxDynamicSharedMemorySize, SMEM_GEMM);
        cudaFuncSetAttribute(attn_tc_kernel, cudaFuncAttributeMaxDynamicSharedMemorySize, SMEM_ATTN);
        attr_done = true;
    }

    __nv_bfloat16 *p_xh, *p_xl, *p_wh, *p_wl;
    cudaGetSymbolAddress((void**)&p_xh, g_xh);
    cudaGetSymbolAddress((void**)&p_xl, g_xl);
    cudaGetSymbolAddress((void**)&p_wh, g_wh);
    cudaGetSymbolAddress((void**)&p_wl, g_wl);

    // 0) Split x and weights into persistent hi/lo bf16
    {
        const int n4x = M * EMBED / 4;           // 1,048,576
        split_fp32_kernel<<<(n4x + 255) / 256, 256>>>(
            (const float4*)x, (uint2*)p_xh, (uint2*)p_xl, n4x);
        const int n4w = EMBED * EMBED / 4;       // 262,144
        const float* Ws[4] = { Wq, Wk, Wv, Wo };
        for (int z = 0; z < 4; z++) {
            split_fp32_kernel<<<(n4w + 255) / 256, 256>>>(
                (const float4*)Ws[z],
                (uint2*)(p_wh + (size_t)z * EMBED * EMBED),
                (uint2*)(p_wl + (size_t)z * EMBED * EMBED), n4w);
        }
    }

    // 1) Q,K,V projections (outputs pre-split; Q pre-scaled by 1/8)
    {
        dim3 grid(EMBED / TN, M / TM, 3);
        qkv_tc_kernel<<<grid, 512, SMEM_GEMM>>>();
    }
    // 2) Flash attention + sin-mix epilogue (output pre-split)
    {
        dim3 grid(S / 256, HEADS, B);
        attn_tc_kernel<<<grid, 512, SMEM_ATTN>>>(qw);
    }
    // 3) Output projection -> fp32 d_out
    {
        dim3 grid(EMBED / TN, M / TM, 1);
        out_tc_kernel<<<grid, 512, SMEM_GEMM>>>(out);
    }
}